// round 13
// baseline (speedup 1.0000x reference)
#include <cuda_runtime.h>
#include <cuda_bf16.h>
#include <math.h>
#include <stdint.h>

#define M_TOTAL 16384
#define D_DIM   2048
#define DI_DIM  256
#define L_SEQ   4096
#define LN_EPS  1e-5f

// ---------------- scratch ----------------
__device__ float g_z  [(size_t)M_TOTAL * DI_DIM];     // z fp32 row-major (gating)
__device__ float g_dg [(size_t)1024 * M_TOTAL];       // dg^T
__device__ float g_h  [(size_t)512  * M_TOTAL];       // h^T fp32
__device__ float g_out[(size_t)M_TOTAL * D_DIM];      // y = out + x

// pre-swizzled tile-blocked operand images (16KB A-tiles, 32KB B-tiles)
__device__ uint8_t g_xp [(size_t)128 * 64 * 16384];   // x  A-tiles [mtile][chunk]
__device__ uint8_t g_zp [(size_t)128 *  8 * 16384];   // z  A-tiles
__device__ uint8_t g_hp [(size_t)128 * 16 * 16384];   // h  A-tiles
__device__ uint8_t g_w1p[(size_t)  1 * 64 * 32768];   // W1 B-tiles [ntile][chunk]
__device__ uint8_t g_w2p[(size_t)  4 *  8 * 32768];   // W2 B-tiles
__device__ uint8_t g_w3p[(size_t)  8 * 16 * 32768];   // W3 B-tiles

// ---------------- arch feature gate ----------------
#if defined(__CUDA_ARCH_FEAT_SM103_ALL) || defined(__CUDA_ARCH_FEAT_SM100_ALL) || \
    defined(__CUDA_ARCH_FEAT_SM101_ALL) || defined(__CUDA_ARCH_SPECIFIC__)
#define TC_OK 1
#else
#define TC_OK 0
#endif

// ---------------- helpers ----------------
__device__ __forceinline__ uint32_t smem_u32(const void* p) {
    uint32_t a;
    asm("{ .reg .u64 t; cvta.to.shared.u64 t, %1; cvt.u32.u64 %0, t; }" : "=r"(a) : "l"(p));
    return a;
}

__device__ __forceinline__ float bf16hi(float a) {
    return __bfloat162float(__float2bfloat16_rn(a));
}
__device__ __forceinline__ uint32_t bf16pack(float a, float b) {
    __nv_bfloat162 t = __floats2bfloat162_rn(a, b);
    return *reinterpret_cast<uint32_t*>(&t);
}
__device__ __forceinline__ uint32_t sw128(uint32_t b) {
    return b ^ ((b >> 3) & 0x70);
}
__device__ __forceinline__ uint32_t ctarank() {
    uint32_t r;
    asm("mov.u32 %0, %%cluster_ctarank;" : "=r"(r));
    return r;
}

#define CLUSTER_SYNC() do { \
    asm volatile("barrier.cluster.arrive.aligned;" ::: "memory"); \
    asm volatile("barrier.cluster.wait.aligned;" ::: "memory"); \
} while (0)

#define MBARRIER_INIT(addr, cnt) \
    asm volatile("mbarrier.init.shared.b64 [%0], %1;" :: "r"(addr), "r"(cnt) : "memory")
#define MBARRIER_EXPECT_TX(mbar, tx) \
    asm volatile("mbarrier.arrive.expect_tx.shared.b64 _, [%0], %1;" \
                 :: "r"(mbar), "r"((uint32_t)(tx)) : "memory")
#define CP_BULK(dst, src, sz, mbar) \
    asm volatile("cp.async.bulk.shared::cta.global.mbarrier::complete_tx::bytes " \
                 "[%0], [%1], %2, [%3];" \
                 :: "r"(dst), "l"(src), "r"((uint32_t)(sz)), "r"(mbar) : "memory")

__device__ __forceinline__ void mbar_wait(uint32_t mbar, uint32_t parity) {
    asm volatile(
        "{\n\t.reg .pred P;\n\t"
        "W0_%=:\n\t"
        "mbarrier.try_wait.parity.acquire.cta.shared::cta.b64 P, [%0], %1, 0x989680;\n\t"
        "@P bra W1_%=;\n\t"
        "bra W0_%=;\n\t"
        "W1_%=:\n\t}"
        :: "r"(mbar), "r"(parity) : "memory");
}

#if TC_OK
// 1D bulk copy with cluster multicast (sm_10xa): delivers data + complete_tx
// to the same SMEM offset in every CTA whose bit is set in mask.
#define CP_BULK_MC(dst, src, sz, mbar, mask) \
    asm volatile("cp.async.bulk.shared::cluster.global.mbarrier::complete_tx::bytes" \
                 ".multicast::cluster [%0], [%1], %2, [%3], %4;" \
                 :: "r"(dst), "l"(src), "r"((uint32_t)(sz)), "r"(mbar), \
                    "h"((uint16_t)(mask)) : "memory")
#define TCGEN05_COMMIT_MC(mbar, mask) \
    asm volatile("tcgen05.commit.cta_group::1.mbarrier::arrive::one.shared::cluster" \
                 ".multicast::cluster.b64 [%0], %1;" \
                 :: "r"((uint32_t)(mbar)), "h"((uint16_t)(mask)) : "memory")
#define TCGEN05_ALLOC(smem_res, ncols) \
    asm volatile("tcgen05.alloc.cta_group::1.sync.aligned.shared::cta.b32 [%0], %1;" \
                 :: "r"((uint32_t)(smem_res)), "r"((uint32_t)(ncols)) : "memory")
#define TCGEN05_DEALLOC(tmem, ncols) \
    asm volatile("tcgen05.dealloc.cta_group::1.sync.aligned.b32 %0, %1;" \
                 :: "r"(tmem), "r"((uint32_t)(ncols)))
#define TCGEN05_RELINQUISH() \
    asm volatile("tcgen05.relinquish_alloc_permit.cta_group::1.sync.aligned;")
#define TCGEN05_FENCE_AFTER() \
    asm volatile("tcgen05.fence::after_thread_sync;" ::: "memory")
#define TCGEN05_WAIT_LD() \
    asm volatile("tcgen05.wait::ld.sync.aligned;" ::: "memory")

#define TCGEN05_LD_X32(r, tmem_addr) \
    asm volatile( \
        "tcgen05.ld.sync.aligned.32x32b.x32.b32 " \
        "{%0, %1, %2, %3, %4, %5, %6, %7, " \
        " %8, %9, %10, %11, %12, %13, %14, %15, " \
        " %16, %17, %18, %19, %20, %21, %22, %23, " \
        " %24, %25, %26, %27, %28, %29, %30, %31}, [%32];" \
        : "=r"((r)[0]),  "=r"((r)[1]),  "=r"((r)[2]),  "=r"((r)[3]), \
          "=r"((r)[4]),  "=r"((r)[5]),  "=r"((r)[6]),  "=r"((r)[7]), \
          "=r"((r)[8]),  "=r"((r)[9]),  "=r"((r)[10]), "=r"((r)[11]), \
          "=r"((r)[12]), "=r"((r)[13]), "=r"((r)[14]), "=r"((r)[15]), \
          "=r"((r)[16]), "=r"((r)[17]), "=r"((r)[18]), "=r"((r)[19]), \
          "=r"((r)[20]), "=r"((r)[21]), "=r"((r)[22]), "=r"((r)[23]), \
          "=r"((r)[24]), "=r"((r)[25]), "=r"((r)[26]), "=r"((r)[27]), \
          "=r"((r)[28]), "=r"((r)[29]), "=r"((r)[30]), "=r"((r)[31]) \
        : "r"(tmem_addr))

__device__ __forceinline__ void mma_bf16(uint32_t d, uint64_t ad, uint64_t bd,
                                         uint32_t idesc, uint32_t en) {
    asm volatile(
        "{\n\t.reg .pred p;\n\t"
        "setp.ne.u32 p, %5, 0;\n\t"
        "tcgen05.mma.cta_group::1.kind::f16 [%0], %1, %2, %3, {%4, %4, %4, %4}, p;\n\t}"
        :: "r"(d), "l"(ad), "l"(bd), "r"(idesc), "r"(0u), "r"(en) : "memory");
}
#else
#define CP_BULK_MC(dst, src, sz, mbar, mask)  do {} while (0)
#define TCGEN05_COMMIT_MC(mbar, mask)         do {} while (0)
#define TCGEN05_ALLOC(smem_res, ncols)  do {} while (0)
#define TCGEN05_DEALLOC(tmem, ncols)    do {} while (0)
#define TCGEN05_RELINQUISH()            do {} while (0)
#define TCGEN05_FENCE_AFTER()           do {} while (0)
#define TCGEN05_WAIT_LD()               do {} while (0)
#define TCGEN05_LD_X32(r, tmem_addr) \
    do { _Pragma("unroll") for (int _i = 0; _i < 32; _i++) (r)[_i] = 0u; } while (0)
__device__ __forceinline__ void mma_bf16(uint32_t, uint64_t, uint64_t, uint32_t, uint32_t) {}
#endif

// SW128 K-major SMEM descriptor (layout=2, ver=1, SBO=64, LBO=1)
__device__ __forceinline__ uint64_t sdesc(uint32_t addr) {
    return 0x4000404000010000ULL | (uint64_t)((addr >> 4) & 0x3FFF);
}

#define STG_OFF  1024
#define STAGE_SZ 49152                       // A 16K (hi|lo packed) + B 32K
#define DEPTH    2
#define GSMEM    (STG_OFF + DEPTH * STAGE_SZ)  // 99,328 B -> 2 CTAs/SM

// idesc kind::f16 bf16: dtype=F32(1@4), atype=BF16(1@7), btype=BF16(1@10), N/8@17, M/16@24
#define IDESC_BF16 ((1u << 4) | (1u << 7) | (1u << 10) | ((256u / 8) << 17) | ((128u / 16) << 24))

// ---------------------------------------------------------------------------
// bf16x3 Ootomo GEMM, bulk-copy pipeline + cluster-pair B multicast.
// Cluster (1,2,1): 2 m-adjacent CTAs share the same B ntile. Rank 0 issues
// ONE multicast bulk B copy (32KB) delivering to both CTAs; each CTA bulk-
// copies its own A (16KB). full[s]: count 1, expect_tx 49152 per CTA.
// empty[s]: count 2; both consumers commit with tcgen05 MULTICAST commit.
// Thread 0 = bulk producer; thread 32 = MMA consumer.
// Tile 128 x 256, 256-col TMEM accumulator, DEPTH=2 stages, 2 CTAs/SM.
// MODE 0: row-major fp32 + packed-tile bf16 hi/lo store (z producer)
// MODE 2: delta/gate epilogue, transposed store into dg^T (EX = z fp32)
// MODE 3: row-major store + residual EX
// ---------------------------------------------------------------------------
template<int MODE>
__global__ void __launch_bounds__(256, 2) __cluster_dims__(1, 2, 1)
gemm_bf16x3(const uint8_t* __restrict__ gA, const uint8_t* __restrict__ gB,
            float* __restrict__ C, uint8_t* __restrict__ Cpk,
            const float* __restrict__ EX, int N, int K)
{
    constexpr int FULL_OFF  = 16;
    constexpr int EMPTY_OFF = 16 + 8 * DEPTH;

    extern __shared__ __align__(1024) char dsm[];
    uint32_t sb = smem_u32(dsm);
    int tid = threadIdx.x, wid = tid >> 5, lane = tid & 31;
    int n0 = blockIdx.x * 256, m0 = blockIdx.y * 128;
    uint32_t rank = ctarank();

    if (wid == 0) TCGEN05_ALLOC(sb, 256);
    if (tid == 0) {
#pragma unroll
        for (int s = 0; s < DEPTH; s++) {
            MBARRIER_INIT(sb + FULL_OFF  + 8 * s, 1);    // expect_tx arrive (local t0)
            MBARRIER_INIT(sb + EMPTY_OFF + 8 * s, 2);    // both consumers' mc commits
        }
    }
    __syncthreads();
    uint32_t tmem;
    asm volatile("ld.shared.b32 %0, [%1];" : "=r"(tmem) : "r"(sb));
    if (wid == 0) TCGEN05_RELINQUISH();

    // all cluster barriers initialized before any multicast may target them
    CLUSTER_SYNC();

    const int NC = K >> 5;                  // 32-fp-element K chunks (NC >= DEPTH)

    if (tid == 0) {
        // ---------------- bulk producer ----------------
        const uint8_t* Abase = gA + (size_t)blockIdx.y * NC * 16384;
        const uint8_t* Bbase = gB + (size_t)blockIdx.x * NC * 32768;
        for (int c = 0; c < NC; c++) {
            int st = c & (DEPTH - 1);
            if (c >= DEPTH)   // stage free once BOTH consumers committed prior round
                mbar_wait(sb + EMPTY_OFF + 8 * st, ((c / DEPTH) & 1) ^ 1u);
            uint32_t sa = sb + STG_OFF + st * STAGE_SZ;
            uint32_t fb = sb + FULL_OFF + 8 * st;
            MBARRIER_EXPECT_TX(fb, 49152);   // 16K local A + 32K multicast B
            CP_BULK(sa, Abase + (size_t)c * 16384, 16384, fb);
            if (rank == 0)
                CP_BULK_MC(sa + 16384, Bbase + (size_t)c * 32768, 32768, fb, 0x3);
        }
    } else if (tid == 32) {
        // ---------------- MMA consumer ----------------
        for (int c = 0; c < NC; c++) {
            int st = c & (DEPTH - 1);
            mbar_wait(sb + FULL_OFF + 8 * st, (uint32_t)((c / DEPTH) & 1));
            uint32_t sa = sb + STG_OFF + st * STAGE_SZ;
            uint64_t ad = sdesc(sa);
            uint64_t bd = sdesc(sa + 16384);
#pragma unroll
            for (int k = 0; k < 2; k++)              // hi*hi
                mma_bf16(tmem, ad + 2 * k, bd + 2 * k, IDESC_BF16, (uint32_t)((c | k) != 0));
#pragma unroll
            for (int k = 0; k < 2; k++)              // hi*lo
                mma_bf16(tmem, ad + 2 * k, bd + 4 + 2 * k, IDESC_BF16, 1u);
#pragma unroll
            for (int k = 0; k < 2; k++)              // lo*hi
                mma_bf16(tmem, ad + 4 + 2 * k, bd + 2 * k, IDESC_BF16, 1u);
            TCGEN05_COMMIT_MC(sb + EMPTY_OFF + 8 * st, 0x3);  // arrive both CTAs
        }
        // final MMA completion (both consumers' last commits)
        mbar_wait(sb + EMPTY_OFF + 8 * ((NC - 1) & (DEPTH - 1)),
                  (uint32_t)(((NC - 1) / DEPTH) & 1));
    }

    __syncthreads();
    TCGEN05_FENCE_AFTER();

    // -------- epilogue: warp w -> rows (w&3)*32, col half (w>>2)*128 --------
    // LDTM double-buffered against the stores.
    int m = m0 + (wid & 3) * 32 + lane;
    int r = m & 127;
    int ccb = (wid >> 2) * 128;
    uint32_t ra[32], rb[32];

    TCGEN05_LD_X32(ra, tmem + ccb);
#pragma unroll
    for (int i = 0; i < 4; i++) {
        int cc = ccb + i * 32;
        uint32_t* cur = (i & 1) ? rb : ra;
        uint32_t* nxt = (i & 1) ? ra : rb;
        TCGEN05_WAIT_LD();                       // cur ready
        if (i < 3) TCGEN05_LD_X32(nxt, tmem + cc + 32);  // prefetch next (async)

        if (MODE == 0) {
            // z fp32 + packed tile store (A-tiles for GEMM2, N chunks = N>>5)
            uint8_t* tb2 = Cpk + ((size_t)(m >> 7) * (N >> 5)) * 16384;
#pragma unroll
            for (int j = 0; j < 32; j += 4) {
                int col = cc + j;
                size_t off = (size_t)m * N + col;
                float4 v = make_float4(__uint_as_float(cur[j]),
                                       __uint_as_float(cur[j + 1]),
                                       __uint_as_float(cur[j + 2]),
                                       __uint_as_float(cur[j + 3]));
                *(float4*)&C[off] = v;
                float hx = bf16hi(v.x), hy = bf16hi(v.y), hz = bf16hi(v.z), hw = bf16hi(v.w);
                uint2 hi = make_uint2(bf16pack(v.x, v.y), bf16pack(v.z, v.w));
                uint2 lo = make_uint2(bf16pack(v.x - hx, v.y - hy),
                                      bf16pack(v.z - hz, v.w - hw));
                int chunk = col >> 5;
                uint32_t bh = (uint32_t)(r * 128) + ((col & 31) >> 3) * 16 + (col & 7) * 2;
                uint8_t* tb3 = tb2 + (size_t)chunk * 16384;
                *(uint2*)(tb3 + sw128(bh))      = hi;
                *(uint2*)(tb3 + sw128(bh + 64)) = lo;
            }
        } else if (MODE == 3) {
#pragma unroll
            for (int j = 0; j < 32; j += 4) {
                size_t off = (size_t)m * N + n0 + cc + j;
                float4 v = make_float4(__uint_as_float(cur[j]),
                                       __uint_as_float(cur[j + 1]),
                                       __uint_as_float(cur[j + 2]),
                                       __uint_as_float(cur[j + 3]));
                float4 r4 = *(const float4*)&EX[off];
                v.x += r4.x; v.y += r4.y; v.z += r4.z; v.w += r4.w;
                *(float4*)&C[off] = v;
            }
        } else {  // MODE 2: delta/gate, transposed store into dg^T
            int jj0 = (n0 + cc) & 511;
            if (jj0 < 256) {
#pragma unroll
                for (int j = 0; j < 32; j++) {
                    float v = __uint_as_float(cur[j]);
                    v = 1.f / (1.f + __expf(-v));
                    C[(size_t)(n0 + cc + j) * M_TOTAL + m] = v;
                }
            } else {
                int ch0 = jj0 - 256;
#pragma unroll
                for (int j = 0; j < 32; j += 4) {
                    float4 zv = *(const float4*)&EX[(size_t)m * DI_DIM + ch0 + j];
                    C[(size_t)(n0 + cc + j + 0) * M_TOTAL + m] = __uint_as_float(cur[j + 0]) * zv.x;
                    C[(size_t)(n0 + cc + j + 1) * M_TOTAL + m] = __uint_as_float(cur[j + 1]) * zv.y;
                    C[(size_t)(n0 + cc + j + 2) * M_TOTAL + m] = __uint_as_float(cur[j + 2]) * zv.z;
                    C[(size_t)(n0 + cc + j + 3) * M_TOTAL + m] = __uint_as_float(cur[j + 3]) * zv.w;
                }
            }
        }
    }

    __syncthreads();
    if (wid == 0) TCGEN05_DEALLOC(tmem, 256);
    // no CTA exits while peer-targeting multicasts/commits may be in flight
    CLUSTER_SYNC();
}

// ---------------------------------------------------------------------------
// prep_all: builds pre-swizzled tile images.
//   [0,8192):     x A-tiles     (mtile = id>>6, chunk = id&63)
//   [8192,8256):  W1 B-tiles    (chunk = id-8192)
//   [8256,8288):  W2 B-tiles    (nt = t>>3, chunk = t&7)
//   [8288,8416):  W3 B-tiles    (nt = t>>4, chunk = t&15)
// ---------------------------------------------------------------------------
__global__ void __launch_bounds__(256)
prep_all(const float* __restrict__ x,
         const float* __restrict__ W_in, const float* __restrict__ W_fwd,
         const float* __restrict__ W_bwd, const float* __restrict__ W_out)
{
    int id = blockIdx.x;
    int tid = threadIdx.x;

    if (id < 8192) {
        // ---- x A-tiles: 128 rows x 32 fp elems -> 16KB ----
        int m0 = (id >> 6) * 128;
        int kc = (id & 63) * 32;
        uint8_t* base = g_xp + (size_t)id * 16384;
        int rrow = tid >> 1;
#pragma unroll
        for (int qq = 0; qq < 2; qq++) {
            int q = (tid & 1) * 2 + qq;
            const float* src = x + (size_t)(m0 + rrow) * D_DIM + kc + q * 8;
            float4 a = *(const float4*)src;
            float4 b = *(const float4*)(src + 4);
            uint4 hi = make_uint4(bf16pack(a.x, a.y), bf16pack(a.z, a.w),
                                  bf16pack(b.x, b.y), bf16pack(b.z, b.w));
            uint4 lo = make_uint4(
                bf16pack(a.x - bf16hi(a.x), a.y - bf16hi(a.y)),
                bf16pack(a.z - bf16hi(a.z), a.w - bf16hi(a.w)),
                bf16pack(b.x - bf16hi(b.x), b.y - bf16hi(b.y)),
                bf16pack(b.z - bf16hi(b.z), b.w - bf16hi(b.w)));
            uint32_t bh = rrow * 128 + q * 16;
            *(uint4*)(base + sw128(bh))      = hi;
            *(uint4*)(base + sw128(bh + 64)) = lo;
        }
        return;
    }

    // ---- weight B-tiles: 256 rows (N) x 32 fp elems (K) -> 32KB ----
    __shared__ float s[32][257];
    const float* src; int srcw, col0, c;
    uint8_t* base;
    if (id < 8256) {
        c = id - 8192; src = W_in; srcw = DI_DIM; col0 = 0;
        base = g_w1p + (size_t)c * 32768;
    } else if (id < 8288) {
        int t = id - 8256; int nt = t >> 3; c = t & 7;
        srcw = 512; col0 = nt * 256;
        if (col0 < 512) { src = W_fwd; }
        else            { src = W_bwd; col0 -= 512; }
        base = g_w2p + (size_t)t * 32768;
    } else {
        int t = id - 8288; int nt = t >> 4; c = t & 15;
        src = W_out; srcw = D_DIM; col0 = nt * 256;
        base = g_w3p + (size_t)t * 32768;
    }
    // load 32 K-rows x 256 N-cols slice (coalesced)
#pragma unroll
    for (int i = 0; i < 32; i++)
        s[i][tid] = src[(size_t)(c * 32 + i) * srcw + col0 + tid];
    __syncthreads();
    // write packed: row = n (tid), 4 q-groups
    int rrow = tid;
#pragma unroll
    for (int q = 0; q < 4; q++) {
        float f[8];
#pragma unroll
        for (int e = 0; e < 8; e++) f[e] = s[q * 8 + e][rrow];
        uint4 hi = make_uint4(bf16pack(f[0], f[1]), bf16pack(f[2], f[3]),
                              bf16pack(f[4], f[5]), bf16pack(f[6], f[7]));
        uint4 lo = make_uint4(
            bf16pack(f[0] - bf16hi(f[0]), f[1] - bf16hi(f[1])),
            bf16pack(f[2] - bf16hi(f[2]), f[3] - bf16hi(f[3])),
            bf16pack(f[4] - bf16hi(f[4]), f[5] - bf16hi(f[5])),
            bf16pack(f[6] - bf16hi(f[6]), f[7] - bf16hi(f[7])));
        uint32_t bh = rrow * 128 + q * 16;
        *(uint4*)(base + sw128(bh))      = hi;
        *(uint4*)(base + sw128(bh + 64)) = lo;
    }
}

// ---------------------------------------------------------------------------
// h_pack: h^T [512][M] fp32 -> pre-swizzled A-tiles for GEMM3.
// grid (chunk=16, mtile=128); tile = 128 rows x 32 k-elems.
// ---------------------------------------------------------------------------
__global__ void __launch_bounds__(256)
h_pack()
{
    __shared__ float s[32][128];
    int c = blockIdx.x, mtile = blockIdx.y;
    int tid = threadIdx.x;
    int m0 = mtile * 128;

#pragma unroll
    for (int i = 0; i < 16; i++) {
        int linear = i * 256 + tid;
        int kl = linear >> 7, ml = linear & 127;
        s[kl][ml] = g_h[(size_t)(c * 32 + kl) * M_TOTAL + m0 + ml];
    }
    __syncthreads();

    uint8_t* base = g_hp + ((size_t)mtile * 16 + c) * 16384;
#pragma unroll
    for (int it = 0; it < 2; it++) {
        int pid = it * 256 + tid;
        int rrow = pid >> 2, q = pid & 3;
        float f[8];
#pragma unroll
        for (int e = 0; e < 8; e++) f[e] = s[q * 8 + e][rrow];
        uint4 hi = make_uint4(bf16pack(f[0], f[1]), bf16pack(f[2], f[3]),
                              bf16pack(f[4], f[5]), bf16pack(f[6], f[7]));
        uint4 lo = make_uint4(
            bf16pack(f[0] - bf16hi(f[0]), f[1] - bf16hi(f[1])),
            bf16pack(f[2] - bf16hi(f[2]), f[3] - bf16hi(f[3])),
            bf16pack(f[4] - bf16hi(f[4]), f[5] - bf16hi(f[5])),
            bf16pack(f[6] - bf16hi(f[6]), f[7] - bf16hi(f[7])));
        uint32_t bh = rrow * 128 + q * 16;
        *(uint4*)(base + sw128(bh))      = hi;
        *(uint4*)(base + sw128(bh + 64)) = lo;
    }
}

// ---------------------------------------------------------------------------
// Gated linear scan: block per (channel, batch, dir)
// ---------------------------------------------------------------------------
__global__ __launch_bounds__(256)
void scan_kernel()
{
    int d = blockIdx.x, bb = blockIdx.y, dir = blockIdx.z;
    const float* dptr = &g_dg[(size_t)(dir * 512 + d)       * M_TOTAL + bb * L_SEQ];
    const float* gptr = &g_dg[(size_t)(dir * 512 + 256 + d) * M_TOTAL + bb * L_SEQ];
    float*       hptr = &g_h [(size_t)(dir * 256 + d)       * M_TOTAL + bb * L_SEQ];

    int tid = threadIdx.x;
    int base = (dir == 0) ? tid * 16 : (L_SEQ - 16 * (tid + 1));

    float tmpd[16], tmpg[16];
#pragma unroll
    for (int q = 0; q < 4; q++) {
        *(float4*)&tmpd[q * 4] = *(const float4*)&dptr[base + q * 4];
        *(float4*)&tmpg[q * 4] = *(const float4*)&gptr[base + q * 4];
    }
    float dl[16], gt[16];
#pragma unroll
    for (int e = 0; e < 16; e++) {
        int src = (dir == 0) ? e : (15 - e);
        dl[e] = tmpd[src];
        gt[e] = tmpg[src];
    }

    float Aseg = 1.f, Bseg = 0.f;
#pragma unroll
    for (int e = 0; e < 16; e++) {
        Aseg = Aseg * dl[e];
        Bseg = fmaf(Bseg, dl[e], gt[e]);
    }

    __shared__ float sA[256], sB[256];
    sA[tid] = Aseg; sB[tid] = Bseg;
    __syncthreads();
#pragma unroll
    for (int off = 1; off < 256; off <<= 1) {
        float pA = 0.f, pB = 0.f;
        bool has = (tid >= off);
        if (has) { pA = sA[tid - off]; pB = sB[tid - off]; }
        __syncthreads();
        if (has) {
            float Ac = sA[tid], Bc = sB[tid];
            sA[tid] = Ac * pA;
            sB[tid] = fmaf(Ac, pB, Bc);
        }
        __syncthreads();
    }

    float h = (tid == 0) ? 0.f : sB[tid - 1];
    float hv[16];
#pragma unroll
    for (int e = 0; e < 16; e++) {
        h = fmaf(h, dl[e], gt[e]);
        hv[e] = h;
    }

    float outv[16];
#pragma unroll
    for (int q = 0; q < 16; q++)
        outv[q] = (dir == 0) ? hv[q] : hv[15 - q];
#pragma unroll
    for (int q = 0; q < 4; q++)
        *(float4*)&hptr[base + q * 4] =
            make_float4(outv[q * 4], outv[q * 4 + 1], outv[q * 4 + 2], outv[q * 4 + 3]);
}

// ---------------------------------------------------------------------------
// LayerNorm over D=2048 per row
// ---------------------------------------------------------------------------
__global__ __launch_bounds__(256)
void ln_kernel(const float* __restrict__ gamma, const float* __restrict__ beta,
               float* __restrict__ out)
{
    int row = blockIdx.x;
    int tid = threadIdx.x;
    const float* yrow = &g_out[(size_t)row * D_DIM];

    float v[8];
    *(float4*)&v[0] = *(const float4*)&yrow[tid * 8];
    *(float4*)&v[4] = *(const float4*)&yrow[tid * 8 + 4];

    float s = 0.f, s2 = 0.f;
#pragma unroll
    for (int e = 0; e < 8; e++) { s += v[e]; s2 = fmaf(v[e], v[e], s2); }

#pragma unroll
    for (int o = 16; o > 0; o >>= 1) {
        s  += __shfl_xor_sync(0xffffffffu, s,  o);
        s2 += __shfl_xor_sync(0xffffffffu, s2, o);
    }
    __shared__ float sh[16];
    int w = tid >> 5, lane = tid & 31;
    if (lane == 0) { sh[w] = s; sh[8 + w] = s2; }
    __syncthreads();
    float S = 0.f, S2 = 0.f;
    if (lane < 8) { S = sh[lane]; S2 = sh[8 + lane]; }
#pragma unroll
    for (int o = 4; o > 0; o >>= 1) {
        S  += __shfl_xor_sync(0xffffffffu, S,  o);
        S2 += __shfl_xor_sync(0xffffffffu, S2, o);
    }
    S  = __shfl_sync(0xffffffffu, S,  0);
    S2 = __shfl_sync(0xffffffffu, S2, 0);

    const float invD = 1.f / (float)D_DIM;
    float mu = S * invD;
    float var = fmaf(S2, invD, -mu * mu);
    float inv = rsqrtf(var + LN_EPS);

    float g[8], be[8];
    *(float4*)&g[0]  = *(const float4*)&gamma[tid * 8];
    *(float4*)&g[4]  = *(const float4*)&gamma[tid * 8 + 4];
    *(float4*)&be[0] = *(const float4*)&beta[tid * 8];
    *(float4*)&be[4] = *(const float4*)&beta[tid * 8 + 4];

    float r[8];
#pragma unroll
    for (int e = 0; e < 8; e++)
        r[e] = fmaf((v[e] - mu) * inv, g[e], be[e]);

    float* orow = &out[(size_t)row * D_DIM];
    *(float4*)&orow[tid * 8]     = make_float4(r[0], r[1], r[2], r[3]);
    *(float4*)&orow[tid * 8 + 4] = make_float4(r[4], r[5], r[6], r[7]);
}

// ---------------------------------------------------------------------------
extern "C" void kernel_launch(void* const* d_in, const int* in_sizes, int n_in,
                              void* d_out, int out_size)
{
    const float* x     = (const float*)d_in[0];
    const float* W_in  = (const float*)d_in[1];
    const float* W_fwd = (const float*)d_in[2];
    const float* W_bwd = (const float*)d_in[3];
    const float* W_out = (const float*)d_in[4];
    const float* gamma = (const float*)d_in[5];
    const float* beta  = (const float*)d_in[6];
    float* out = (float*)d_out;

    float *zp, *dgp, *op;
    uint8_t *xp, *zpk, *hp, *w1p, *w2p, *w3p;
    cudaGetSymbolAddress((void**)&zp,  g_z);
    cudaGetSymbolAddress((void**)&dgp, g_dg);
    cudaGetSymbolAddress((void**)&op,  g_out);
    cudaGetSymbolAddress((void**)&xp,  g_xp);
    cudaGetSymbolAddress((void**)&zpk, g_zp);
    cudaGetSymbolAddress((void**)&hp,  g_hp);
    cudaGetSymbolAddress((void**)&w1p, g_w1p);
    cudaGetSymbolAddress((void**)&w2p, g_w2p);
    cudaGetSymbolAddress((void**)&w3p, g_w3p);

    cudaFuncSetAttribute((const void*)gemm_bf16x3<0>,
                         cudaFuncAttributeMaxDynamicSharedMemorySize, GSMEM);
    cudaFuncSetAttribute((const void*)gemm_bf16x3<2>,
                         cudaFuncAttributeMaxDynamicSharedMemorySize, GSMEM);
    cudaFuncSetAttribute((const void*)gemm_bf16x3<3>,
                         cudaFuncAttributeMaxDynamicSharedMemorySize, GSMEM);

    // operand preparation: pre-swizzled tile images
    prep_all<<<8416, 256>>>(x, W_in, W_fwd, W_bwd, W_out);

    // z = x @ W_in  (fp32 + packed-tile epilogue)
    gemm_bf16x3<0><<<dim3(1, M_TOTAL / 128), 256, GSMEM>>>(
        xp, w1p, zp, zpk, nullptr, DI_DIM, D_DIM);

    // dg^T = act(z @ [W_fwd|W_bwd])^T
    gemm_bf16x3<2><<<dim3(4, M_TOTAL / 128), 256, GSMEM>>>(
        zpk, w2p, dgp, nullptr, zp, 1024, DI_DIM);

    // bidirectional gated scans -> h^T
    scan_kernel<<<dim3(DI_DIM, 4, 2), 256>>>();

    // h^T -> packed A-tiles
    h_pack<<<dim3(16, 128), 256>>>();

    // y = h @ W_out + x
    gemm_bf16x3<3><<<dim3(8, M_TOTAL / 128), 256, GSMEM>>>(
        hp, w3p, op, nullptr, x, D_DIM, 512);

    // LayerNorm
    ln_kernel<<<M_TOTAL, 256>>>(gamma, beta, out);
}

// round 14
// speedup vs baseline: 1.0183x; 1.0183x over previous
#include <cuda_runtime.h>
#include <cuda_bf16.h>
#include <math.h>
#include <stdint.h>

#define M_TOTAL 16384
#define D_DIM   2048
#define DI_DIM  256
#define L_SEQ   4096
#define LN_EPS  1e-5f

// ---------------- scratch ----------------
__device__ float g_z  [(size_t)M_TOTAL * DI_DIM];     // z fp32 row-major (gating)
__device__ float g_dg [(size_t)1024 * M_TOTAL];       // dg^T
__device__ float g_h  [(size_t)512  * M_TOTAL];       // h^T fp32
__device__ float g_out[(size_t)M_TOTAL * D_DIM];      // y = out + x

// pre-swizzled tile-blocked operand images (16KB A-tiles, 32KB B-tiles)
__device__ uint8_t g_xp [(size_t)128 * 64 * 16384];   // x  A-tiles [mtile][chunk]
__device__ uint8_t g_zp [(size_t)128 *  8 * 16384];   // z  A-tiles
__device__ uint8_t g_hp [(size_t)128 * 16 * 16384];   // h  A-tiles
__device__ uint8_t g_w1p[(size_t)  1 * 64 * 32768];   // W1 B-tiles [ntile][chunk]
__device__ uint8_t g_w2p[(size_t)  4 *  8 * 32768];   // W2 B-tiles
__device__ uint8_t g_w3p[(size_t)  8 * 16 * 32768];   // W3 B-tiles

// ---------------- arch feature gate ----------------
#if defined(__CUDA_ARCH_FEAT_SM103_ALL) || defined(__CUDA_ARCH_FEAT_SM100_ALL) || \
    defined(__CUDA_ARCH_FEAT_SM101_ALL) || defined(__CUDA_ARCH_SPECIFIC__)
#define TC_OK 1
#else
#define TC_OK 0
#endif

// ---------------- helpers ----------------
__device__ __forceinline__ uint32_t smem_u32(const void* p) {
    uint32_t a;
    asm("{ .reg .u64 t; cvta.to.shared.u64 t, %1; cvt.u32.u64 %0, t; }" : "=r"(a) : "l"(p));
    return a;
}

__device__ __forceinline__ float bf16hi(float a) {
    return __bfloat162float(__float2bfloat16_rn(a));
}
__device__ __forceinline__ uint32_t bf16pack(float a, float b) {
    __nv_bfloat162 t = __floats2bfloat162_rn(a, b);
    return *reinterpret_cast<uint32_t*>(&t);
}
__device__ __forceinline__ uint32_t sw128(uint32_t b) {
    return b ^ ((b >> 3) & 0x70);
}
__device__ __forceinline__ uint32_t ctarank() {
    uint32_t r;
    asm("mov.u32 %0, %%cluster_ctarank;" : "=r"(r));
    return r;
}

#define CLUSTER_SYNC() do { \
    asm volatile("barrier.cluster.arrive.aligned;" ::: "memory"); \
    asm volatile("barrier.cluster.wait.aligned;" ::: "memory"); \
} while (0)

#define MBARRIER_INIT(addr, cnt) \
    asm volatile("mbarrier.init.shared.b64 [%0], %1;" :: "r"(addr), "r"(cnt) : "memory")
#define MBARRIER_EXPECT_TX(mbar, tx) \
    asm volatile("mbarrier.arrive.expect_tx.shared.b64 _, [%0], %1;" \
                 :: "r"(mbar), "r"((uint32_t)(tx)) : "memory")
#define CP_BULK(dst, src, sz, mbar) \
    asm volatile("cp.async.bulk.shared::cta.global.mbarrier::complete_tx::bytes " \
                 "[%0], [%1], %2, [%3];" \
                 :: "r"(dst), "l"(src), "r"((uint32_t)(sz)), "r"(mbar) : "memory")

__device__ __forceinline__ void mbar_wait(uint32_t mbar, uint32_t parity) {
    asm volatile(
        "{\n\t.reg .pred P;\n\t"
        "W0_%=:\n\t"
        "mbarrier.try_wait.parity.acquire.cta.shared::cta.b64 P, [%0], %1, 0x989680;\n\t"
        "@P bra W1_%=;\n\t"
        "bra W0_%=;\n\t"
        "W1_%=:\n\t}"
        :: "r"(mbar), "r"(parity) : "memory");
}

#if TC_OK
#define CP_BULK_MC(dst, src, sz, mbar, mask) \
    asm volatile("cp.async.bulk.shared::cluster.global.mbarrier::complete_tx::bytes" \
                 ".multicast::cluster [%0], [%1], %2, [%3], %4;" \
                 :: "r"(dst), "l"(src), "r"((uint32_t)(sz)), "r"(mbar), \
                    "h"((uint16_t)(mask)) : "memory")
#define TCGEN05_COMMIT_MC(mbar, mask) \
    asm volatile("tcgen05.commit.cta_group::1.mbarrier::arrive::one.shared::cluster" \
                 ".multicast::cluster.b64 [%0], %1;" \
                 :: "r"((uint32_t)(mbar)), "h"((uint16_t)(mask)) : "memory")
#define TCGEN05_COMMIT(mbar) \
    asm volatile("tcgen05.commit.cta_group::1.mbarrier::arrive::one.shared::cluster.b64 [%0];" \
                 :: "r"((uint32_t)(mbar)) : "memory")
#define TCGEN05_ALLOC(smem_res, ncols) \
    asm volatile("tcgen05.alloc.cta_group::1.sync.aligned.shared::cta.b32 [%0], %1;" \
                 :: "r"((uint32_t)(smem_res)), "r"((uint32_t)(ncols)) : "memory")
#define TCGEN05_DEALLOC(tmem, ncols) \
    asm volatile("tcgen05.dealloc.cta_group::1.sync.aligned.b32 %0, %1;" \
                 :: "r"(tmem), "r"((uint32_t)(ncols)))
#define TCGEN05_RELINQUISH() \
    asm volatile("tcgen05.relinquish_alloc_permit.cta_group::1.sync.aligned;")
#define TCGEN05_FENCE_AFTER() \
    asm volatile("tcgen05.fence::after_thread_sync;" ::: "memory")
#define TCGEN05_WAIT_LD() \
    asm volatile("tcgen05.wait::ld.sync.aligned;" ::: "memory")

#define TCGEN05_LD_X32(r, tmem_addr) \
    asm volatile( \
        "tcgen05.ld.sync.aligned.32x32b.x32.b32 " \
        "{%0, %1, %2, %3, %4, %5, %6, %7, " \
        " %8, %9, %10, %11, %12, %13, %14, %15, " \
        " %16, %17, %18, %19, %20, %21, %22, %23, " \
        " %24, %25, %26, %27, %28, %29, %30, %31}, [%32];" \
        : "=r"((r)[0]),  "=r"((r)[1]),  "=r"((r)[2]),  "=r"((r)[3]), \
          "=r"((r)[4]),  "=r"((r)[5]),  "=r"((r)[6]),  "=r"((r)[7]), \
          "=r"((r)[8]),  "=r"((r)[9]),  "=r"((r)[10]), "=r"((r)[11]), \
          "=r"((r)[12]), "=r"((r)[13]), "=r"((r)[14]), "=r"((r)[15]), \
          "=r"((r)[16]), "=r"((r)[17]), "=r"((r)[18]), "=r"((r)[19]), \
          "=r"((r)[20]), "=r"((r)[21]), "=r"((r)[22]), "=r"((r)[23]), \
          "=r"((r)[24]), "=r"((r)[25]), "=r"((r)[26]), "=r"((r)[27]), \
          "=r"((r)[28]), "=r"((r)[29]), "=r"((r)[30]), "=r"((r)[31]) \
        : "r"(tmem_addr))

__device__ __forceinline__ void mma_bf16(uint32_t d, uint64_t ad, uint64_t bd,
                                         uint32_t idesc, uint32_t en) {
    asm volatile(
        "{\n\t.reg .pred p;\n\t"
        "setp.ne.u32 p, %5, 0;\n\t"
        "tcgen05.mma.cta_group::1.kind::f16 [%0], %1, %2, %3, {%4, %4, %4, %4}, p;\n\t}"
        :: "r"(d), "l"(ad), "l"(bd), "r"(idesc), "r"(0u), "r"(en) : "memory");
}
#else
#define CP_BULK_MC(dst, src, sz, mbar, mask)  do {} while (0)
#define TCGEN05_COMMIT_MC(mbar, mask)         do {} while (0)
#define TCGEN05_COMMIT(mbar)            do {} while (0)
#define TCGEN05_ALLOC(smem_res, ncols)  do {} while (0)
#define TCGEN05_DEALLOC(tmem, ncols)    do {} while (0)
#define TCGEN05_RELINQUISH()            do {} while (0)
#define TCGEN05_FENCE_AFTER()           do {} while (0)
#define TCGEN05_WAIT_LD()               do {} while (0)
#define TCGEN05_LD_X32(r, tmem_addr) \
    do { _Pragma("unroll") for (int _i = 0; _i < 32; _i++) (r)[_i] = 0u; } while (0)
__device__ __forceinline__ void mma_bf16(uint32_t, uint64_t, uint64_t, uint32_t, uint32_t) {}
#endif

// SW128 K-major SMEM descriptor (layout=2, ver=1, SBO=64, LBO=1)
__device__ __forceinline__ uint64_t sdesc(uint32_t addr) {
    return 0x4000404000010000ULL | (uint64_t)((addr >> 4) & 0x3FFF);
}

#define STG_OFF  1024
#define STAGE_SZ 49152                       // A 16K (hi|lo packed) + B 32K
#define DEPTH    2
#define GSMEM    (STG_OFF + DEPTH * STAGE_SZ)  // 99,328 B -> 2 CTAs/SM

// idesc kind::f16 bf16: dtype=F32(1@4), atype=BF16(1@7), btype=BF16(1@10), N/8@17, M/16@24
#define IDESC_BF16 ((1u << 4) | (1u << 7) | (1u << 10) | ((256u / 8) << 17) | ((128u / 16) << 24))

// ---------------------------------------------------------------------------
// bf16x3 Ootomo GEMM, bulk-copy pipeline (NON-cluster; R12-exact).
// MODE 0: row-major fp32 + packed-tile bf16 hi/lo store (z producer)
// MODE 2: delta/gate epilogue, transposed store into dg^T (EX = z fp32)
// MODE 3: row-major store + residual EX
// ---------------------------------------------------------------------------
template<int MODE>
__global__ void __launch_bounds__(256, 2)
gemm_bf16x3(const uint8_t* __restrict__ gA, const uint8_t* __restrict__ gB,
            float* __restrict__ C, uint8_t* __restrict__ Cpk,
            const float* __restrict__ EX, int N, int K)
{
    constexpr int FULL_OFF  = 16;
    constexpr int EMPTY_OFF = 16 + 8 * DEPTH;

    extern __shared__ __align__(1024) char dsm[];
    uint32_t sb = smem_u32(dsm);
    int tid = threadIdx.x, wid = tid >> 5, lane = tid & 31;
    int n0 = blockIdx.x * 256, m0 = blockIdx.y * 128;

    if (wid == 0) TCGEN05_ALLOC(sb, 256);
    if (tid == 0) {
#pragma unroll
        for (int s = 0; s < DEPTH; s++) {
            MBARRIER_INIT(sb + FULL_OFF  + 8 * s, 1);
            MBARRIER_INIT(sb + EMPTY_OFF + 8 * s, 1);
        }
    }
    __syncthreads();
    uint32_t tmem;
    asm volatile("ld.shared.b32 %0, [%1];" : "=r"(tmem) : "r"(sb));
    if (wid == 0) TCGEN05_RELINQUISH();

    const int NC = K >> 5;

    if (tid == 0) {
        const uint8_t* Abase = gA + (size_t)blockIdx.y * NC * 16384;
        const uint8_t* Bbase = gB + (size_t)blockIdx.x * NC * 32768;
        for (int c = 0; c < NC; c++) {
            int st = c & (DEPTH - 1);
            if (c >= DEPTH)
                mbar_wait(sb + EMPTY_OFF + 8 * st, ((c / DEPTH) & 1) ^ 1u);
            uint32_t sa = sb + STG_OFF + st * STAGE_SZ;
            uint32_t fb = sb + FULL_OFF + 8 * st;
            MBARRIER_EXPECT_TX(fb, 49152);
            CP_BULK(sa,         Abase + (size_t)c * 16384, 16384, fb);
            CP_BULK(sa + 16384, Bbase + (size_t)c * 32768, 32768, fb);
        }
    } else if (tid == 32) {
        for (int c = 0; c < NC; c++) {
            int st = c & (DEPTH - 1);
            mbar_wait(sb + FULL_OFF + 8 * st, (uint32_t)((c / DEPTH) & 1));
            uint32_t sa = sb + STG_OFF + st * STAGE_SZ;
            uint64_t ad = sdesc(sa);
            uint64_t bd = sdesc(sa + 16384);
#pragma unroll
            for (int k = 0; k < 2; k++)
                mma_bf16(tmem, ad + 2 * k, bd + 2 * k, IDESC_BF16, (uint32_t)((c | k) != 0));
#pragma unroll
            for (int k = 0; k < 2; k++)
                mma_bf16(tmem, ad + 2 * k, bd + 4 + 2 * k, IDESC_BF16, 1u);
#pragma unroll
            for (int k = 0; k < 2; k++)
                mma_bf16(tmem, ad + 4 + 2 * k, bd + 2 * k, IDESC_BF16, 1u);
            TCGEN05_COMMIT(sb + EMPTY_OFF + 8 * st);
        }
        mbar_wait(sb + EMPTY_OFF + 8 * ((NC - 1) & (DEPTH - 1)),
                  (uint32_t)(((NC - 1) / DEPTH) & 1));
    }

    __syncthreads();
    TCGEN05_FENCE_AFTER();

    // -------- epilogue --------
    int m = m0 + (wid & 3) * 32 + lane;
    int r = m & 127;
    int ccb = (wid >> 2) * 128;
    uint32_t ra[32], rb[32];

    TCGEN05_LD_X32(ra, tmem + ccb);
#pragma unroll
    for (int i = 0; i < 4; i++) {
        int cc = ccb + i * 32;
        uint32_t* cur = (i & 1) ? rb : ra;
        uint32_t* nxt = (i & 1) ? ra : rb;
        TCGEN05_WAIT_LD();
        if (i < 3) TCGEN05_LD_X32(nxt, tmem + cc + 32);

        if (MODE == 0) {
            uint8_t* tb2 = Cpk + ((size_t)(m >> 7) * (N >> 5)) * 16384;
#pragma unroll
            for (int j = 0; j < 32; j += 4) {
                int col = cc + j;
                size_t off = (size_t)m * N + col;
                float4 v = make_float4(__uint_as_float(cur[j]),
                                       __uint_as_float(cur[j + 1]),
                                       __uint_as_float(cur[j + 2]),
                                       __uint_as_float(cur[j + 3]));
                *(float4*)&C[off] = v;
                float hx = bf16hi(v.x), hy = bf16hi(v.y), hz = bf16hi(v.z), hw = bf16hi(v.w);
                uint2 hi = make_uint2(bf16pack(v.x, v.y), bf16pack(v.z, v.w));
                uint2 lo = make_uint2(bf16pack(v.x - hx, v.y - hy),
                                      bf16pack(v.z - hz, v.w - hw));
                int chunk = col >> 5;
                uint32_t bh = (uint32_t)(r * 128) + ((col & 31) >> 3) * 16 + (col & 7) * 2;
                uint8_t* tb3 = tb2 + (size_t)chunk * 16384;
                *(uint2*)(tb3 + sw128(bh))      = hi;
                *(uint2*)(tb3 + sw128(bh + 64)) = lo;
            }
        } else if (MODE == 3) {
#pragma unroll
            for (int j = 0; j < 32; j += 4) {
                size_t off = (size_t)m * N + n0 + cc + j;
                float4 v = make_float4(__uint_as_float(cur[j]),
                                       __uint_as_float(cur[j + 1]),
                                       __uint_as_float(cur[j + 2]),
                                       __uint_as_float(cur[j + 3]));
                float4 r4 = *(const float4*)&EX[off];
                v.x += r4.x; v.y += r4.y; v.z += r4.z; v.w += r4.w;
                *(float4*)&C[off] = v;
            }
        } else {  // MODE 2
            int jj0 = (n0 + cc) & 511;
            if (jj0 < 256) {
#pragma unroll
                for (int j = 0; j < 32; j++) {
                    float v = __uint_as_float(cur[j]);
                    v = 1.f / (1.f + __expf(-v));
                    C[(size_t)(n0 + cc + j) * M_TOTAL + m] = v;
                }
            } else {
                int ch0 = jj0 - 256;
#pragma unroll
                for (int j = 0; j < 32; j += 4) {
                    float4 zv = *(const float4*)&EX[(size_t)m * DI_DIM + ch0 + j];
                    C[(size_t)(n0 + cc + j + 0) * M_TOTAL + m] = __uint_as_float(cur[j + 0]) * zv.x;
                    C[(size_t)(n0 + cc + j + 1) * M_TOTAL + m] = __uint_as_float(cur[j + 1]) * zv.y;
                    C[(size_t)(n0 + cc + j + 2) * M_TOTAL + m] = __uint_as_float(cur[j + 2]) * zv.z;
                    C[(size_t)(n0 + cc + j + 3) * M_TOTAL + m] = __uint_as_float(cur[j + 3]) * zv.w;
                }
            }
        }
    }

    __syncthreads();
    if (wid == 0) TCGEN05_DEALLOC(tmem, 256);
}

// ---------------------------------------------------------------------------
// gemm_mc: GEMM3 only. Cluster (1,2,1): pair of m-adjacent CTAs shares one
// multicast B copy per chunk. empty[s] count=2, multicast tcgen05 commits.
// Epilogue = MODE 3 (residual add, row-major store).
// ---------------------------------------------------------------------------
__global__ void __launch_bounds__(256, 2) __cluster_dims__(1, 2, 1)
gemm_mc(const uint8_t* __restrict__ gA, const uint8_t* __restrict__ gB,
        float* __restrict__ C, const float* __restrict__ EX, int N, int K)
{
    constexpr int FULL_OFF  = 16;
    constexpr int EMPTY_OFF = 16 + 8 * DEPTH;

    extern __shared__ __align__(1024) char dsm[];
    uint32_t sb = smem_u32(dsm);
    int tid = threadIdx.x, wid = tid >> 5, lane = tid & 31;
    int n0 = blockIdx.x * 256, m0 = blockIdx.y * 128;
    uint32_t rank = ctarank();

    if (wid == 0) TCGEN05_ALLOC(sb, 256);
    if (tid == 0) {
#pragma unroll
        for (int s = 0; s < DEPTH; s++) {
            MBARRIER_INIT(sb + FULL_OFF  + 8 * s, 1);
            MBARRIER_INIT(sb + EMPTY_OFF + 8 * s, 2);   // both consumers' mc commits
        }
    }
    __syncthreads();
    uint32_t tmem;
    asm volatile("ld.shared.b32 %0, [%1];" : "=r"(tmem) : "r"(sb));
    if (wid == 0) TCGEN05_RELINQUISH();

    CLUSTER_SYNC();   // barriers visible before any peer-targeting multicast

    const int NC = K >> 5;

    if (tid == 0) {
        const uint8_t* Abase = gA + (size_t)blockIdx.y * NC * 16384;
        const uint8_t* Bbase = gB + (size_t)blockIdx.x * NC * 32768;
        for (int c = 0; c < NC; c++) {
            int st = c & (DEPTH - 1);
            if (c >= DEPTH)
                mbar_wait(sb + EMPTY_OFF + 8 * st, ((c / DEPTH) & 1) ^ 1u);
            uint32_t sa = sb + STG_OFF + st * STAGE_SZ;
            uint32_t fb = sb + FULL_OFF + 8 * st;
            MBARRIER_EXPECT_TX(fb, 49152);   // 16K local A + 32K multicast B
            CP_BULK(sa, Abase + (size_t)c * 16384, 16384, fb);
            if (rank == 0)
                CP_BULK_MC(sa + 16384, Bbase + (size_t)c * 32768, 32768, fb, 0x3);
        }
    } else if (tid == 32) {
        for (int c = 0; c < NC; c++) {
            int st = c & (DEPTH - 1);
            mbar_wait(sb + FULL_OFF + 8 * st, (uint32_t)((c / DEPTH) & 1));
            uint32_t sa = sb + STG_OFF + st * STAGE_SZ;
            uint64_t ad = sdesc(sa);
            uint64_t bd = sdesc(sa + 16384);
#pragma unroll
            for (int k = 0; k < 2; k++)
                mma_bf16(tmem, ad + 2 * k, bd + 2 * k, IDESC_BF16, (uint32_t)((c | k) != 0));
#pragma unroll
            for (int k = 0; k < 2; k++)
                mma_bf16(tmem, ad + 2 * k, bd + 4 + 2 * k, IDESC_BF16, 1u);
#pragma unroll
            for (int k = 0; k < 2; k++)
                mma_bf16(tmem, ad + 4 + 2 * k, bd + 2 * k, IDESC_BF16, 1u);
            TCGEN05_COMMIT_MC(sb + EMPTY_OFF + 8 * st, 0x3);
        }
        mbar_wait(sb + EMPTY_OFF + 8 * ((NC - 1) & (DEPTH - 1)),
                  (uint32_t)(((NC - 1) / DEPTH) & 1));
    }

    __syncthreads();
    TCGEN05_FENCE_AFTER();

    // -------- epilogue (MODE 3) --------
    int m = m0 + (wid & 3) * 32 + lane;
    int ccb = (wid >> 2) * 128;
    uint32_t ra[32], rb[32];

    TCGEN05_LD_X32(ra, tmem + ccb);
#pragma unroll
    for (int i = 0; i < 4; i++) {
        int cc = ccb + i * 32;
        uint32_t* cur = (i & 1) ? rb : ra;
        uint32_t* nxt = (i & 1) ? ra : rb;
        TCGEN05_WAIT_LD();
        if (i < 3) TCGEN05_LD_X32(nxt, tmem + cc + 32);
#pragma unroll
        for (int j = 0; j < 32; j += 4) {
            size_t off = (size_t)m * N + n0 + cc + j;
            float4 v = make_float4(__uint_as_float(cur[j]),
                                   __uint_as_float(cur[j + 1]),
                                   __uint_as_float(cur[j + 2]),
                                   __uint_as_float(cur[j + 3]));
            float4 r4 = *(const float4*)&EX[off];
            v.x += r4.x; v.y += r4.y; v.z += r4.z; v.w += r4.w;
            *(float4*)&C[off] = v;
        }
    }

    __syncthreads();
    if (wid == 0) TCGEN05_DEALLOC(tmem, 256);
    CLUSTER_SYNC();   // no exit while peer-targeting ops may be in flight
}

// ---------------------------------------------------------------------------
// prep_all: builds pre-swizzled tile images.
// ---------------------------------------------------------------------------
__global__ void __launch_bounds__(256)
prep_all(const float* __restrict__ x,
         const float* __restrict__ W_in, const float* __restrict__ W_fwd,
         const float* __restrict__ W_bwd, const float* __restrict__ W_out)
{
    int id = blockIdx.x;
    int tid = threadIdx.x;

    if (id < 8192) {
        int m0 = (id >> 6) * 128;
        int kc = (id & 63) * 32;
        uint8_t* base = g_xp + (size_t)id * 16384;
        int rrow = tid >> 1;
#pragma unroll
        for (int qq = 0; qq < 2; qq++) {
            int q = (tid & 1) * 2 + qq;
            const float* src = x + (size_t)(m0 + rrow) * D_DIM + kc + q * 8;
            float4 a = *(const float4*)src;
            float4 b = *(const float4*)(src + 4);
            uint4 hi = make_uint4(bf16pack(a.x, a.y), bf16pack(a.z, a.w),
                                  bf16pack(b.x, b.y), bf16pack(b.z, b.w));
            uint4 lo = make_uint4(
                bf16pack(a.x - bf16hi(a.x), a.y - bf16hi(a.y)),
                bf16pack(a.z - bf16hi(a.z), a.w - bf16hi(a.w)),
                bf16pack(b.x - bf16hi(b.x), b.y - bf16hi(b.y)),
                bf16pack(b.z - bf16hi(b.z), b.w - bf16hi(b.w)));
            uint32_t bh = rrow * 128 + q * 16;
            *(uint4*)(base + sw128(bh))      = hi;
            *(uint4*)(base + sw128(bh + 64)) = lo;
        }
        return;
    }

    __shared__ float s[32][257];
    const float* src; int srcw, col0, c;
    uint8_t* base;
    if (id < 8256) {
        c = id - 8192; src = W_in; srcw = DI_DIM; col0 = 0;
        base = g_w1p + (size_t)c * 32768;
    } else if (id < 8288) {
        int t = id - 8256; int nt = t >> 3; c = t & 7;
        srcw = 512; col0 = nt * 256;
        if (col0 < 512) { src = W_fwd; }
        else            { src = W_bwd; col0 -= 512; }
        base = g_w2p + (size_t)t * 32768;
    } else {
        int t = id - 8288; int nt = t >> 4; c = t & 15;
        src = W_out; srcw = D_DIM; col0 = nt * 256;
        base = g_w3p + (size_t)t * 32768;
    }
#pragma unroll
    for (int i = 0; i < 32; i++)
        s[i][tid] = src[(size_t)(c * 32 + i) * srcw + col0 + tid];
    __syncthreads();
    int rrow = tid;
#pragma unroll
    for (int q = 0; q < 4; q++) {
        float f[8];
#pragma unroll
        for (int e = 0; e < 8; e++) f[e] = s[q * 8 + e][rrow];
        uint4 hi = make_uint4(bf16pack(f[0], f[1]), bf16pack(f[2], f[3]),
                              bf16pack(f[4], f[5]), bf16pack(f[6], f[7]));
        uint4 lo = make_uint4(
            bf16pack(f[0] - bf16hi(f[0]), f[1] - bf16hi(f[1])),
            bf16pack(f[2] - bf16hi(f[2]), f[3] - bf16hi(f[3])),
            bf16pack(f[4] - bf16hi(f[4]), f[5] - bf16hi(f[5])),
            bf16pack(f[6] - bf16hi(f[6]), f[7] - bf16hi(f[7])));
        uint32_t bh = rrow * 128 + q * 16;
        *(uint4*)(base + sw128(bh))      = hi;
        *(uint4*)(base + sw128(bh + 64)) = lo;
    }
}

// ---------------------------------------------------------------------------
// h_pack: h^T [512][M] fp32 -> pre-swizzled A-tiles for GEMM3.
// ---------------------------------------------------------------------------
__global__ void __launch_bounds__(256)
h_pack()
{
    __shared__ float s[32][128];
    int c = blockIdx.x, mtile = blockIdx.y;
    int tid = threadIdx.x;
    int m0 = mtile * 128;

#pragma unroll
    for (int i = 0; i < 16; i++) {
        int linear = i * 256 + tid;
        int kl = linear >> 7, ml = linear & 127;
        s[kl][ml] = g_h[(size_t)(c * 32 + kl) * M_TOTAL + m0 + ml];
    }
    __syncthreads();

    uint8_t* base = g_hp + ((size_t)mtile * 16 + c) * 16384;
#pragma unroll
    for (int it = 0; it < 2; it++) {
        int pid = it * 256 + tid;
        int rrow = pid >> 2, q = pid & 3;
        float f[8];
#pragma unroll
        for (int e = 0; e < 8; e++) f[e] = s[q * 8 + e][rrow];
        uint4 hi = make_uint4(bf16pack(f[0], f[1]), bf16pack(f[2], f[3]),
                              bf16pack(f[4], f[5]), bf16pack(f[6], f[7]));
        uint4 lo = make_uint4(
            bf16pack(f[0] - bf16hi(f[0]), f[1] - bf16hi(f[1])),
            bf16pack(f[2] - bf16hi(f[2]), f[3] - bf16hi(f[3])),
            bf16pack(f[4] - bf16hi(f[4]), f[5] - bf16hi(f[5])),
            bf16pack(f[6] - bf16hi(f[6]), f[7] - bf16hi(f[7])));
        uint32_t bh = rrow * 128 + q * 16;
        *(uint4*)(base + sw128(bh))      = hi;
        *(uint4*)(base + sw128(bh + 64)) = lo;
    }
}

// ---------------------------------------------------------------------------
// Gated linear scan: block per (channel, batch, dir)
// ---------------------------------------------------------------------------
__global__ __launch_bounds__(256)
void scan_kernel()
{
    int d = blockIdx.x, bb = blockIdx.y, dir = blockIdx.z;
    const float* dptr = &g_dg[(size_t)(dir * 512 + d)       * M_TOTAL + bb * L_SEQ];
    const float* gptr = &g_dg[(size_t)(dir * 512 + 256 + d) * M_TOTAL + bb * L_SEQ];
    float*       hptr = &g_h [(size_t)(dir * 256 + d)       * M_TOTAL + bb * L_SEQ];

    int tid = threadIdx.x;
    int base = (dir == 0) ? tid * 16 : (L_SEQ - 16 * (tid + 1));

    float tmpd[16], tmpg[16];
#pragma unroll
    for (int q = 0; q < 4; q++) {
        *(float4*)&tmpd[q * 4] = *(const float4*)&dptr[base + q * 4];
        *(float4*)&tmpg[q * 4] = *(const float4*)&gptr[base + q * 4];
    }
    float dl[16], gt[16];
#pragma unroll
    for (int e = 0; e < 16; e++) {
        int src = (dir == 0) ? e : (15 - e);
        dl[e] = tmpd[src];
        gt[e] = tmpg[src];
    }

    float Aseg = 1.f, Bseg = 0.f;
#pragma unroll
    for (int e = 0; e < 16; e++) {
        Aseg = Aseg * dl[e];
        Bseg = fmaf(Bseg, dl[e], gt[e]);
    }

    __shared__ float sA[256], sB[256];
    sA[tid] = Aseg; sB[tid] = Bseg;
    __syncthreads();
#pragma unroll
    for (int off = 1; off < 256; off <<= 1) {
        float pA = 0.f, pB = 0.f;
        bool has = (tid >= off);
        if (has) { pA = sA[tid - off]; pB = sB[tid - off]; }
        __syncthreads();
        if (has) {
            float Ac = sA[tid], Bc = sB[tid];
            sA[tid] = Ac * pA;
            sB[tid] = fmaf(Ac, pB, Bc);
        }
        __syncthreads();
    }

    float h = (tid == 0) ? 0.f : sB[tid - 1];
    float hv[16];
#pragma unroll
    for (int e = 0; e < 16; e++) {
        h = fmaf(h, dl[e], gt[e]);
        hv[e] = h;
    }

    float outv[16];
#pragma unroll
    for (int q = 0; q < 16; q++)
        outv[q] = (dir == 0) ? hv[q] : hv[15 - q];
#pragma unroll
    for (int q = 0; q < 4; q++)
        *(float4*)&hptr[base + q * 4] =
            make_float4(outv[q * 4], outv[q * 4 + 1], outv[q * 4 + 2], outv[q * 4 + 3]);
}

// ---------------------------------------------------------------------------
// LayerNorm over D=2048 per row
// ---------------------------------------------------------------------------
__global__ __launch_bounds__(256)
void ln_kernel(const float* __restrict__ gamma, const float* __restrict__ beta,
               float* __restrict__ out)
{
    int row = blockIdx.x;
    int tid = threadIdx.x;
    const float* yrow = &g_out[(size_t)row * D_DIM];

    float v[8];
    *(float4*)&v[0] = *(const float4*)&yrow[tid * 8];
    *(float4*)&v[4] = *(const float4*)&yrow[tid * 8 + 4];

    float s = 0.f, s2 = 0.f;
#pragma unroll
    for (int e = 0; e < 8; e++) { s += v[e]; s2 = fmaf(v[e], v[e], s2); }

#pragma unroll
    for (int o = 16; o > 0; o >>= 1) {
        s  += __shfl_xor_sync(0xffffffffu, s,  o);
        s2 += __shfl_xor_sync(0xffffffffu, s2, o);
    }
    __shared__ float sh[16];
    int w = tid >> 5, lane = tid & 31;
    if (lane == 0) { sh[w] = s; sh[8 + w] = s2; }
    __syncthreads();
    float S = 0.f, S2 = 0.f;
    if (lane < 8) { S = sh[lane]; S2 = sh[8 + lane]; }
#pragma unroll
    for (int o = 4; o > 0; o >>= 1) {
        S  += __shfl_xor_sync(0xffffffffu, S,  o);
        S2 += __shfl_xor_sync(0xffffffffu, S2, o);
    }
    S  = __shfl_sync(0xffffffffu, S,  0);
    S2 = __shfl_sync(0xffffffffu, S2, 0);

    const float invD = 1.f / (float)D_DIM;
    float mu = S * invD;
    float var = fmaf(S2, invD, -mu * mu);
    float inv = rsqrtf(var + LN_EPS);

    float g[8], be[8];
    *(float4*)&g[0]  = *(const float4*)&gamma[tid * 8];
    *(float4*)&g[4]  = *(const float4*)&gamma[tid * 8 + 4];
    *(float4*)&be[0] = *(const float4*)&beta[tid * 8];
    *(float4*)&be[4] = *(const float4*)&beta[tid * 8 + 4];

    float r[8];
#pragma unroll
    for (int e = 0; e < 8; e++)
        r[e] = fmaf((v[e] - mu) * inv, g[e], be[e]);

    float* orow = &out[(size_t)row * D_DIM];
    *(float4*)&orow[tid * 8]     = make_float4(r[0], r[1], r[2], r[3]);
    *(float4*)&orow[tid * 8 + 4] = make_float4(r[4], r[5], r[6], r[7]);
}

// ---------------------------------------------------------------------------
extern "C" void kernel_launch(void* const* d_in, const int* in_sizes, int n_in,
                              void* d_out, int out_size)
{
    const float* x     = (const float*)d_in[0];
    const float* W_in  = (const float*)d_in[1];
    const float* W_fwd = (const float*)d_in[2];
    const float* W_bwd = (const float*)d_in[3];
    const float* W_out = (const float*)d_in[4];
    const float* gamma = (const float*)d_in[5];
    const float* beta  = (const float*)d_in[6];
    float* out = (float*)d_out;

    float *zp, *dgp, *op;
    uint8_t *xp, *zpk, *hp, *w1p, *w2p, *w3p;
    cudaGetSymbolAddress((void**)&zp,  g_z);
    cudaGetSymbolAddress((void**)&dgp, g_dg);
    cudaGetSymbolAddress((void**)&op,  g_out);
    cudaGetSymbolAddress((void**)&xp,  g_xp);
    cudaGetSymbolAddress((void**)&zpk, g_zp);
    cudaGetSymbolAddress((void**)&hp,  g_hp);
    cudaGetSymbolAddress((void**)&w1p, g_w1p);
    cudaGetSymbolAddress((void**)&w2p, g_w2p);
    cudaGetSymbolAddress((void**)&w3p, g_w3p);

    cudaFuncSetAttribute((const void*)gemm_bf16x3<0>,
                         cudaFuncAttributeMaxDynamicSharedMemorySize, GSMEM);
    cudaFuncSetAttribute((const void*)gemm_bf16x3<2>,
                         cudaFuncAttributeMaxDynamicSharedMemorySize, GSMEM);
    cudaFuncSetAttribute((const void*)gemm_mc,
                         cudaFuncAttributeMaxDynamicSharedMemorySize, GSMEM);

    // operand preparation: pre-swizzled tile images
    prep_all<<<8416, 256>>>(x, W_in, W_fwd, W_bwd, W_out);

    // z = x @ W_in  (fp32 + packed-tile epilogue)
    gemm_bf16x3<0><<<dim3(1, M_TOTAL / 128), 256, GSMEM>>>(
        xp, w1p, zp, zpk, nullptr, DI_DIM, D_DIM);

    // dg^T = act(z @ [W_fwd|W_bwd])^T
    gemm_bf16x3<2><<<dim3(4, M_TOTAL / 128), 256, GSMEM>>>(
        zpk, w2p, dgp, nullptr, zp, 1024, DI_DIM);

    // bidirectional gated scans -> h^T
    scan_kernel<<<dim3(DI_DIM, 4, 2), 256>>>();

    // h^T -> packed A-tiles
    h_pack<<<dim3(16, 128), 256>>>();

    // y = h @ W_out + x   (cluster-pair B multicast)
    gemm_mc<<<dim3(8, M_TOTAL / 128), 256, GSMEM>>>(
        hp, w3p, op, x, D_DIM, 512);

    // LayerNorm
    ln_kernel<<<M_TOTAL, 256>>>(gamma, beta, out);
}

// round 16
// speedup vs baseline: 1.0899x; 1.0703x over previous
#include <cuda_runtime.h>
#include <cuda_bf16.h>
#include <math.h>
#include <stdint.h>

#define M_TOTAL 16384
#define D_DIM   2048
#define DI_DIM  256
#define L_SEQ   4096
#define LN_EPS  1e-5f

// ---------------- scratch ----------------
__device__ float g_z  [(size_t)M_TOTAL * DI_DIM];     // z fp32 row-major (gating)
__device__ float g_zab[(size_t)2 * M_TOTAL * DI_DIM]; // z K-split partials
__device__ float g_dg [(size_t)1024 * M_TOTAL];       // dg^T
__device__ float g_h  [(size_t)512  * M_TOTAL];       // h^T fp32
__device__ float g_out[(size_t)M_TOTAL * D_DIM];      // y = out + x

// pre-swizzled tile-blocked operand images (16KB A-tiles, 32KB B-tiles)
__device__ uint8_t g_xp [(size_t)128 * 64 * 16384];   // x  A-tiles [mtile][chunk]
__device__ uint8_t g_zp [(size_t)128 *  8 * 16384];   // z  A-tiles
__device__ uint8_t g_hp [(size_t)128 * 16 * 16384];   // h  A-tiles
__device__ uint8_t g_w1p[(size_t)  1 * 64 * 32768];   // W1 B-tiles [ntile][chunk]
__device__ uint8_t g_w2p[(size_t)  4 *  8 * 32768];   // W2 B-tiles
__device__ uint8_t g_w3p[(size_t)  8 * 16 * 32768];   // W3 B-tiles

// ---------------- arch feature gate ----------------
#if defined(__CUDA_ARCH_FEAT_SM103_ALL) || defined(__CUDA_ARCH_FEAT_SM100_ALL) || \
    defined(__CUDA_ARCH_FEAT_SM101_ALL) || defined(__CUDA_ARCH_SPECIFIC__)
#define TC_OK 1
#else
#define TC_OK 0
#endif

// ---------------- helpers ----------------
__device__ __forceinline__ uint32_t smem_u32(const void* p) {
    uint32_t a;
    asm("{ .reg .u64 t; cvta.to.shared.u64 t, %1; cvt.u32.u64 %0, t; }" : "=r"(a) : "l"(p));
    return a;
}

__device__ __forceinline__ float bf16hi(float a) {
    return __bfloat162float(__float2bfloat16_rn(a));
}
__device__ __forceinline__ uint32_t bf16pack(float a, float b) {
    __nv_bfloat162 t = __floats2bfloat162_rn(a, b);
    return *reinterpret_cast<uint32_t*>(&t);
}
__device__ __forceinline__ uint32_t sw128(uint32_t b) {
    return b ^ ((b >> 3) & 0x70);
}

#define MBARRIER_INIT(addr, cnt) \
    asm volatile("mbarrier.init.shared.b64 [%0], %1;" :: "r"(addr), "r"(cnt) : "memory")
#define MBARRIER_EXPECT_TX(mbar, tx) \
    asm volatile("mbarrier.arrive.expect_tx.shared.b64 _, [%0], %1;" \
                 :: "r"(mbar), "r"((uint32_t)(tx)) : "memory")
#define CP_BULK(dst, src, sz, mbar) \
    asm volatile("cp.async.bulk.shared::cta.global.mbarrier::complete_tx::bytes " \
                 "[%0], [%1], %2, [%3];" \
                 :: "r"(dst), "l"(src), "r"((uint32_t)(sz)), "r"(mbar) : "memory")

__device__ __forceinline__ void mbar_wait(uint32_t mbar, uint32_t parity) {
    asm volatile(
        "{\n\t.reg .pred P;\n\t"
        "W0_%=:\n\t"
        "mbarrier.try_wait.parity.acquire.cta.shared::cta.b64 P, [%0], %1, 0x989680;\n\t"
        "@P bra W1_%=;\n\t"
        "bra W0_%=;\n\t"
        "W1_%=:\n\t}"
        :: "r"(mbar), "r"(parity) : "memory");
}

#if TC_OK
#define TCGEN05_COMMIT(mbar) \
    asm volatile("tcgen05.commit.cta_group::1.mbarrier::arrive::one.shared::cluster.b64 [%0];" \
                 :: "r"((uint32_t)(mbar)) : "memory")
#define TCGEN05_ALLOC(smem_res, ncols) \
    asm volatile("tcgen05.alloc.cta_group::1.sync.aligned.shared::cta.b32 [%0], %1;" \
                 :: "r"((uint32_t)(smem_res)), "r"((uint32_t)(ncols)) : "memory")
#define TCGEN05_DEALLOC(tmem, ncols) \
    asm volatile("tcgen05.dealloc.cta_group::1.sync.aligned.b32 %0, %1;" \
                 :: "r"(tmem), "r"((uint32_t)(ncols)))
#define TCGEN05_RELINQUISH() \
    asm volatile("tcgen05.relinquish_alloc_permit.cta_group::1.sync.aligned;")
#define TCGEN05_FENCE_AFTER() \
    asm volatile("tcgen05.fence::after_thread_sync;" ::: "memory")
#define TCGEN05_WAIT_LD() \
    asm volatile("tcgen05.wait::ld.sync.aligned;" ::: "memory")

#define TCGEN05_LD_X32(r, tmem_addr) \
    asm volatile( \
        "tcgen05.ld.sync.aligned.32x32b.x32.b32 " \
        "{%0, %1, %2, %3, %4, %5, %6, %7, " \
        " %8, %9, %10, %11, %12, %13, %14, %15, " \
        " %16, %17, %18, %19, %20, %21, %22, %23, " \
        " %24, %25, %26, %27, %28, %29, %30, %31}, [%32];" \
        : "=r"((r)[0]),  "=r"((r)[1]),  "=r"((r)[2]),  "=r"((r)[3]), \
          "=r"((r)[4]),  "=r"((r)[5]),  "=r"((r)[6]),  "=r"((r)[7]), \
          "=r"((r)[8]),  "=r"((r)[9]),  "=r"((r)[10]), "=r"((r)[11]), \
          "=r"((r)[12]), "=r"((r)[13]), "=r"((r)[14]), "=r"((r)[15]), \
          "=r"((r)[16]), "=r"((r)[17]), "=r"((r)[18]), "=r"((r)[19]), \
          "=r"((r)[20]), "=r"((r)[21]), "=r"((r)[22]), "=r"((r)[23]), \
          "=r"((r)[24]), "=r"((r)[25]), "=r"((r)[26]), "=r"((r)[27]), \
          "=r"((r)[28]), "=r"((r)[29]), "=r"((r)[30]), "=r"((r)[31]) \
        : "r"(tmem_addr))

__device__ __forceinline__ void mma_bf16(uint32_t d, uint64_t ad, uint64_t bd,
                                         uint32_t idesc, uint32_t en) {
    asm volatile(
        "{\n\t.reg .pred p;\n\t"
        "setp.ne.u32 p, %5, 0;\n\t"
        "tcgen05.mma.cta_group::1.kind::f16 [%0], %1, %2, %3, {%4, %4, %4, %4}, p;\n\t}"
        :: "r"(d), "l"(ad), "l"(bd), "r"(idesc), "r"(0u), "r"(en) : "memory");
}
#else
#define TCGEN05_COMMIT(mbar)            do {} while (0)
#define TCGEN05_ALLOC(smem_res, ncols)  do {} while (0)
#define TCGEN05_DEALLOC(tmem, ncols)    do {} while (0)
#define TCGEN05_RELINQUISH()            do {} while (0)
#define TCGEN05_FENCE_AFTER()           do {} while (0)
#define TCGEN05_WAIT_LD()               do {} while (0)
#define TCGEN05_LD_X32(r, tmem_addr) \
    do { _Pragma("unroll") for (int _i = 0; _i < 32; _i++) (r)[_i] = 0u; } while (0)
__device__ __forceinline__ void mma_bf16(uint32_t, uint64_t, uint64_t, uint32_t, uint32_t) {}
#endif

// SW128 K-major SMEM descriptor (layout=2, ver=1, SBO=64, LBO=1)
__device__ __forceinline__ uint64_t sdesc(uint32_t addr) {
    return 0x4000404000010000ULL | (uint64_t)((addr >> 4) & 0x3FFF);
}

#define STG_OFF  1024
#define STAGE_SZ 49152                       // A 16K (hi|lo packed) + B 32K
#define DEPTH    2
#define GSMEM    (STG_OFF + DEPTH * STAGE_SZ)  // 99,328 B -> 2 CTAs/SM

// idesc kind::f16 bf16: dtype=F32(1@4), atype=BF16(1@7), btype=BF16(1@10), N/8@17, M/16@24
#define IDESC_BF16 ((1u << 4) | (1u << 7) | (1u << 10) | ((256u / 8) << 17) | ((128u / 16) << 24))

// ---------------------------------------------------------------------------
// bf16x3 Ootomo GEMM, bulk-copy pipeline (R12-exact MMA path, BN=256).
// MODE 1: K-split partial producer: blockIdx.x = K-half; plain fp32 store
//         into C + blockIdx.x * M*256 (full 256 cols per CTA).
// MODE 2: delta/gate epilogue, transposed store into dg^T (EX = z fp32)
// MODE 3: row-major store + residual EX
// ---------------------------------------------------------------------------
template<int MODE>
__global__ void __launch_bounds__(256, 2)
gemm_bf16x3(const uint8_t* __restrict__ gA, const uint8_t* __restrict__ gB,
            float* __restrict__ C, uint8_t* __restrict__ Cpk,
            const float* __restrict__ EX, int N, int K)
{
    constexpr int FULL_OFF  = 16;
    constexpr int EMPTY_OFF = 16 + 8 * DEPTH;

    extern __shared__ __align__(1024) char dsm[];
    uint32_t sb = smem_u32(dsm);
    int tid = threadIdx.x, wid = tid >> 5, lane = tid & 31;
    int n0 = (MODE == 1) ? 0 : blockIdx.x * 256;
    int m0 = blockIdx.y * 128;
    if (MODE == 1) C += (size_t)blockIdx.x * M_TOTAL * DI_DIM;

    if (wid == 0) TCGEN05_ALLOC(sb, 256);
    if (tid == 0) {
#pragma unroll
        for (int s = 0; s < DEPTH; s++) {
            MBARRIER_INIT(sb + FULL_OFF  + 8 * s, 1);
            MBARRIER_INIT(sb + EMPTY_OFF + 8 * s, 1);
        }
    }
    __syncthreads();
    uint32_t tmem;
    asm volatile("ld.shared.b32 %0, [%1];" : "=r"(tmem) : "r"(sb));
    if (wid == 0) TCGEN05_RELINQUISH();

    const int NC = K >> 5;

    if (tid == 0) {
        const uint8_t* Abase;
        const uint8_t* Bbase;
        if (MODE == 1) {   // K-split: x A-tiles have 64 chunks/mtile; half x uses [x*32, x*32+32)
            Abase = gA + ((size_t)blockIdx.y * 64 + (size_t)blockIdx.x * NC) * 16384;
            Bbase = gB + (size_t)blockIdx.x * NC * 32768;
        } else {
            Abase = gA + (size_t)blockIdx.y * NC * 16384;
            Bbase = gB + (size_t)blockIdx.x * NC * 32768;
        }
        for (int c = 0; c < NC; c++) {
            int st = c & (DEPTH - 1);
            if (c >= DEPTH)
                mbar_wait(sb + EMPTY_OFF + 8 * st, ((c / DEPTH) & 1) ^ 1u);
            uint32_t sa = sb + STG_OFF + st * STAGE_SZ;
            uint32_t fb = sb + FULL_OFF + 8 * st;
            MBARRIER_EXPECT_TX(fb, 49152);
            CP_BULK(sa,         Abase + (size_t)c * 16384, 16384, fb);
            CP_BULK(sa + 16384, Bbase + (size_t)c * 32768, 32768, fb);
        }
    } else if (tid == 32) {
        for (int c = 0; c < NC; c++) {
            int st = c & (DEPTH - 1);
            mbar_wait(sb + FULL_OFF + 8 * st, (uint32_t)((c / DEPTH) & 1));
            uint32_t sa = sb + STG_OFF + st * STAGE_SZ;
            uint64_t ad = sdesc(sa);
            uint64_t bd = sdesc(sa + 16384);
#pragma unroll
            for (int k = 0; k < 2; k++)
                mma_bf16(tmem, ad + 2 * k, bd + 2 * k, IDESC_BF16, (uint32_t)((c | k) != 0));
#pragma unroll
            for (int k = 0; k < 2; k++)
                mma_bf16(tmem, ad + 2 * k, bd + 4 + 2 * k, IDESC_BF16, 1u);
#pragma unroll
            for (int k = 0; k < 2; k++)
                mma_bf16(tmem, ad + 4 + 2 * k, bd + 2 * k, IDESC_BF16, 1u);
            TCGEN05_COMMIT(sb + EMPTY_OFF + 8 * st);
        }
        mbar_wait(sb + EMPTY_OFF + 8 * ((NC - 1) & (DEPTH - 1)),
                  (uint32_t)(((NC - 1) / DEPTH) & 1));
    }

    __syncthreads();
    TCGEN05_FENCE_AFTER();

    // -------- epilogue: warp w -> rows (w&3)*32, col half (w>>2)*128 --------
    int m = m0 + (wid & 3) * 32 + lane;
    int ccb = (wid >> 2) * 128;
    uint32_t ra[32], rb[32];

    TCGEN05_LD_X32(ra, tmem + ccb);
#pragma unroll
    for (int i = 0; i < 4; i++) {
        int cc = ccb + i * 32;
        uint32_t* cur = (i & 1) ? rb : ra;
        uint32_t* nxt = (i & 1) ? ra : rb;
        TCGEN05_WAIT_LD();
        if (i < 3) TCGEN05_LD_X32(nxt, tmem + cc + 32);

        if (MODE == 1) {
#pragma unroll
            for (int j = 0; j < 32; j += 4) {
                size_t off = (size_t)m * N + cc + j;
                float4 v = make_float4(__uint_as_float(cur[j]),
                                       __uint_as_float(cur[j + 1]),
                                       __uint_as_float(cur[j + 2]),
                                       __uint_as_float(cur[j + 3]));
                *(float4*)&C[off] = v;
            }
        } else if (MODE == 3) {
#pragma unroll
            for (int j = 0; j < 32; j += 4) {
                size_t off = (size_t)m * N + n0 + cc + j;
                float4 v = make_float4(__uint_as_float(cur[j]),
                                       __uint_as_float(cur[j + 1]),
                                       __uint_as_float(cur[j + 2]),
                                       __uint_as_float(cur[j + 3]));
                float4 r4 = *(const float4*)&EX[off];
                v.x += r4.x; v.y += r4.y; v.z += r4.z; v.w += r4.w;
                *(float4*)&C[off] = v;
            }
        } else {  // MODE 2
            int jj0 = (n0 + cc) & 511;
            if (jj0 < 256) {
#pragma unroll
                for (int j = 0; j < 32; j++) {
                    float v = __uint_as_float(cur[j]);
                    v = 1.f / (1.f + __expf(-v));
                    C[(size_t)(n0 + cc + j) * M_TOTAL + m] = v;
                }
            } else {
                int ch0 = jj0 - 256;
#pragma unroll
                for (int j = 0; j < 32; j += 4) {
                    float4 zv = *(const float4*)&EX[(size_t)m * DI_DIM + ch0 + j];
                    C[(size_t)(n0 + cc + j + 0) * M_TOTAL + m] = __uint_as_float(cur[j + 0]) * zv.x;
                    C[(size_t)(n0 + cc + j + 1) * M_TOTAL + m] = __uint_as_float(cur[j + 1]) * zv.y;
                    C[(size_t)(n0 + cc + j + 2) * M_TOTAL + m] = __uint_as_float(cur[j + 2]) * zv.z;
                    C[(size_t)(n0 + cc + j + 3) * M_TOTAL + m] = __uint_as_float(cur[j + 3]) * zv.w;
                }
            }
        }
    }

    __syncthreads();
    if (wid == 0) TCGEN05_DEALLOC(tmem, 256);
}

// ---------------------------------------------------------------------------
// z_combine: z = za + zb (fp32) + packed zpk A-tiles for GEMM2.
// grid (chunk=8, mtile=128), 256 threads; thread -> row tid>>1, 16 cols.
// ---------------------------------------------------------------------------
__global__ void __launch_bounds__(256)
z_combine()
{
    int c = blockIdx.x, mtile = blockIdx.y;
    int tid = threadIdx.x;
    int row = tid >> 1;                 // 0..127
    int q2 = (tid & 1) * 2;             // first q-group of this thread's pair
    int m = mtile * 128 + row;
    int col = c * 32 + q2 * 8;          // 16 consecutive cols

    const float* pa = g_zab + (size_t)m * DI_DIM + col;
    const float* pb = g_zab + (size_t)M_TOTAL * DI_DIM + (size_t)m * DI_DIM + col;
    float* pz = g_z + (size_t)m * DI_DIM + col;

    float f[16];
#pragma unroll
    for (int i = 0; i < 4; i++) {
        float4 a = ((const float4*)pa)[i];
        float4 b = ((const float4*)pb)[i];
        float4 s = make_float4(a.x + b.x, a.y + b.y, a.z + b.z, a.w + b.w);
        f[i * 4 + 0] = s.x; f[i * 4 + 1] = s.y; f[i * 4 + 2] = s.z; f[i * 4 + 3] = s.w;
        ((float4*)pz)[i] = s;
    }

    uint8_t* tile = g_zp + ((size_t)mtile * 8 + c) * 16384;
#pragma unroll
    for (int qq = 0; qq < 2; qq++) {
        int q = q2 + qq;
        const float* g = &f[qq * 8];
        uint4 hi = make_uint4(bf16pack(g[0], g[1]), bf16pack(g[2], g[3]),
                              bf16pack(g[4], g[5]), bf16pack(g[6], g[7]));
        uint4 lo = make_uint4(
            bf16pack(g[0] - bf16hi(g[0]), g[1] - bf16hi(g[1])),
            bf16pack(g[2] - bf16hi(g[2]), g[3] - bf16hi(g[3])),
            bf16pack(g[4] - bf16hi(g[4]), g[5] - bf16hi(g[5])),
            bf16pack(g[6] - bf16hi(g[6]), g[7] - bf16hi(g[7])));
        uint32_t bh = (uint32_t)row * 128 + q * 16;
        *(uint4*)(tile + sw128(bh))      = hi;
        *(uint4*)(tile + sw128(bh + 64)) = lo;
    }
}

// ---------------------------------------------------------------------------
// prep_all (R12-exact): builds pre-swizzled tile images.
//   [0,8192):     x A-tiles     (mtile = id>>6, chunk = id&63)
//   [8192,8256):  W1 B-tiles    (chunk = id-8192)
//   [8256,8288):  W2 B-tiles    (nt = t>>3, chunk = t&7)
//   [8288,8416):  W3 B-tiles    (nt = t>>4, chunk = t&15)
// ---------------------------------------------------------------------------
__global__ void __launch_bounds__(256)
prep_all(const float* __restrict__ x,
         const float* __restrict__ W_in, const float* __restrict__ W_fwd,
         const float* __restrict__ W_bwd, const float* __restrict__ W_out)
{
    int id = blockIdx.x;
    int tid = threadIdx.x;

    if (id < 8192) {
        int m0 = (id >> 6) * 128;
        int kc = (id & 63) * 32;
        uint8_t* base = g_xp + (size_t)id * 16384;
        int rrow = tid >> 1;
#pragma unroll
        for (int qq = 0; qq < 2; qq++) {
            int q = (tid & 1) * 2 + qq;
            const float* src = x + (size_t)(m0 + rrow) * D_DIM + kc + q * 8;
            float4 a = *(const float4*)src;
            float4 b = *(const float4*)(src + 4);
            uint4 hi = make_uint4(bf16pack(a.x, a.y), bf16pack(a.z, a.w),
                                  bf16pack(b.x, b.y), bf16pack(b.z, b.w));
            uint4 lo = make_uint4(
                bf16pack(a.x - bf16hi(a.x), a.y - bf16hi(a.y)),
                bf16pack(a.z - bf16hi(a.z), a.w - bf16hi(a.w)),
                bf16pack(b.x - bf16hi(b.x), b.y - bf16hi(b.y)),
                bf16pack(b.z - bf16hi(b.z), b.w - bf16hi(b.w)));
            uint32_t bh = rrow * 128 + q * 16;
            *(uint4*)(base + sw128(bh))      = hi;
            *(uint4*)(base + sw128(bh + 64)) = lo;
        }
        return;
    }

    __shared__ float s[32][257];
    const float* src; int srcw, col0, c;
    uint8_t* base;
    if (id < 8256) {
        c = id - 8192; src = W_in; srcw = DI_DIM; col0 = 0;
        base = g_w1p + (size_t)c * 32768;
    } else if (id < 8288) {
        int t = id - 8256; int nt = t >> 3; c = t & 7;
        srcw = 512; col0 = nt * 256;
        if (col0 < 512) { src = W_fwd; }
        else            { src = W_bwd; col0 -= 512; }
        base = g_w2p + (size_t)t * 32768;
    } else {
        int t = id - 8288; int nt = t >> 4; c = t & 15;
        src = W_out; srcw = D_DIM; col0 = nt * 256;
        base = g_w3p + (size_t)t * 32768;
    }
#pragma unroll
    for (int i = 0; i < 32; i++)
        s[i][tid] = src[(size_t)(c * 32 + i) * srcw + col0 + tid];
    __syncthreads();
    int rrow = tid;
#pragma unroll
    for (int q = 0; q < 4; q++) {
        float f[8];
#pragma unroll
        for (int e = 0; e < 8; e++) f[e] = s[q * 8 + e][rrow];
        uint4 hi = make_uint4(bf16pack(f[0], f[1]), bf16pack(f[2], f[3]),
                              bf16pack(f[4], f[5]), bf16pack(f[6], f[7]));
        uint4 lo = make_uint4(
            bf16pack(f[0] - bf16hi(f[0]), f[1] - bf16hi(f[1])),
            bf16pack(f[2] - bf16hi(f[2]), f[3] - bf16hi(f[3])),
            bf16pack(f[4] - bf16hi(f[4]), f[5] - bf16hi(f[5])),
            bf16pack(f[6] - bf16hi(f[6]), f[7] - bf16hi(f[7])));
        uint32_t bh = rrow * 128 + q * 16;
        *(uint4*)(base + sw128(bh))      = hi;
        *(uint4*)(base + sw128(bh + 64)) = lo;
    }
}

// ---------------------------------------------------------------------------
// h_pack: h^T [512][M] fp32 -> pre-swizzled A-tiles for GEMM3.
// ---------------------------------------------------------------------------
__global__ void __launch_bounds__(256)
h_pack()
{
    __shared__ float s[32][128];
    int c = blockIdx.x, mtile = blockIdx.y;
    int tid = threadIdx.x;
    int m0 = mtile * 128;

#pragma unroll
    for (int i = 0; i < 16; i++) {
        int linear = i * 256 + tid;
        int kl = linear >> 7, ml = linear & 127;
        s[kl][ml] = g_h[(size_t)(c * 32 + kl) * M_TOTAL + m0 + ml];
    }
    __syncthreads();

    uint8_t* base = g_hp + ((size_t)mtile * 16 + c) * 16384;
#pragma unroll
    for (int it = 0; it < 2; it++) {
        int pid = it * 256 + tid;
        int rrow = pid >> 2, q = pid & 3;
        float f[8];
#pragma unroll
        for (int e = 0; e < 8; e++) f[e] = s[q * 8 + e][rrow];
        uint4 hi = make_uint4(bf16pack(f[0], f[1]), bf16pack(f[2], f[3]),
                              bf16pack(f[4], f[5]), bf16pack(f[6], f[7]));
        uint4 lo = make_uint4(
            bf16pack(f[0] - bf16hi(f[0]), f[1] - bf16hi(f[1])),
            bf16pack(f[2] - bf16hi(f[2]), f[3] - bf16hi(f[3])),
            bf16pack(f[4] - bf16hi(f[4]), f[5] - bf16hi(f[5])),
            bf16pack(f[6] - bf16hi(f[6]), f[7] - bf16hi(f[7])));
        uint32_t bh = rrow * 128 + q * 16;
        *(uint4*)(base + sw128(bh))      = hi;
        *(uint4*)(base + sw128(bh + 64)) = lo;
    }
}

// ---------------------------------------------------------------------------
// Gated linear scan: block per (channel, batch, dir)
// ---------------------------------------------------------------------------
__global__ __launch_bounds__(256)
void scan_kernel()
{
    int d = blockIdx.x, bb = blockIdx.y, dir = blockIdx.z;
    const float* dptr = &g_dg[(size_t)(dir * 512 + d)       * M_TOTAL + bb * L_SEQ];
    const float* gptr = &g_dg[(size_t)(dir * 512 + 256 + d) * M_TOTAL + bb * L_SEQ];
    float*       hptr = &g_h [(size_t)(dir * 256 + d)       * M_TOTAL + bb * L_SEQ];

    int tid = threadIdx.x;
    int base = (dir == 0) ? tid * 16 : (L_SEQ - 16 * (tid + 1));

    float tmpd[16], tmpg[16];
#pragma unroll
    for (int q = 0; q < 4; q++) {
        *(float4*)&tmpd[q * 4] = *(const float4*)&dptr[base + q * 4];
        *(float4*)&tmpg[q * 4] = *(const float4*)&gptr[base + q * 4];
    }
    float dl[16], gt[16];
#pragma unroll
    for (int e = 0; e < 16; e++) {
        int src = (dir == 0) ? e : (15 - e);
        dl[e] = tmpd[src];
        gt[e] = tmpg[src];
    }

    float Aseg = 1.f, Bseg = 0.f;
#pragma unroll
    for (int e = 0; e < 16; e++) {
        Aseg = Aseg * dl[e];
        Bseg = fmaf(Bseg, dl[e], gt[e]);
    }

    __shared__ float sA[256], sB[256];
    sA[tid] = Aseg; sB[tid] = Bseg;
    __syncthreads();
#pragma unroll
    for (int off = 1; off < 256; off <<= 1) {
        float pA = 0.f, pB = 0.f;
        bool has = (tid >= off);
        if (has) { pA = sA[tid - off]; pB = sB[tid - off]; }
        __syncthreads();
        if (has) {
            float Ac = sA[tid], Bc = sB[tid];
            sA[tid] = Ac * pA;
            sB[tid] = fmaf(Ac, pB, Bc);
        }
        __syncthreads();
    }

    float h = (tid == 0) ? 0.f : sB[tid - 1];
    float hv[16];
#pragma unroll
    for (int e = 0; e < 16; e++) {
        h = fmaf(h, dl[e], gt[e]);
        hv[e] = h;
    }

    float outv[16];
#pragma unroll
    for (int q = 0; q < 16; q++)
        outv[q] = (dir == 0) ? hv[q] : hv[15 - q];
#pragma unroll
    for (int q = 0; q < 4; q++)
        *(float4*)&hptr[base + q * 4] =
            make_float4(outv[q * 4], outv[q * 4 + 1], outv[q * 4 + 2], outv[q * 4 + 3]);
}

// ---------------------------------------------------------------------------
// LayerNorm over D=2048 per row
// ---------------------------------------------------------------------------
__global__ __launch_bounds__(256)
void ln_kernel(const float* __restrict__ gamma, const float* __restrict__ beta,
               float* __restrict__ out)
{
    int row = blockIdx.x;
    int tid = threadIdx.x;
    const float* yrow = &g_out[(size_t)row * D_DIM];

    float v[8];
    *(float4*)&v[0] = *(const float4*)&yrow[tid * 8];
    *(float4*)&v[4] = *(const float4*)&yrow[tid * 8 + 4];

    float s = 0.f, s2 = 0.f;
#pragma unroll
    for (int e = 0; e < 8; e++) { s += v[e]; s2 = fmaf(v[e], v[e], s2); }

#pragma unroll
    for (int o = 16; o > 0; o >>= 1) {
        s  += __shfl_xor_sync(0xffffffffu, s,  o);
        s2 += __shfl_xor_sync(0xffffffffu, s2, o);
    }
    __shared__ float sh[16];
    int w = tid >> 5, lane = tid & 31;
    if (lane == 0) { sh[w] = s; sh[8 + w] = s2; }
    __syncthreads();
    float S = 0.f, S2 = 0.f;
    if (lane < 8) { S = sh[lane]; S2 = sh[8 + lane]; }
#pragma unroll
    for (int o = 4; o > 0; o >>= 1) {
        S  += __shfl_xor_sync(0xffffffffu, S,  o);
        S2 += __shfl_xor_sync(0xffffffffu, S2, o);
    }
    S  = __shfl_sync(0xffffffffu, S,  0);
    S2 = __shfl_sync(0xffffffffu, S2, 0);

    const float invD = 1.f / (float)D_DIM;
    float mu = S * invD;
    float var = fmaf(S2, invD, -mu * mu);
    float inv = rsqrtf(var + LN_EPS);

    float g[8], be[8];
    *(float4*)&g[0]  = *(const float4*)&gamma[tid * 8];
    *(float4*)&g[4]  = *(const float4*)&gamma[tid * 8 + 4];
    *(float4*)&be[0] = *(const float4*)&beta[tid * 8];
    *(float4*)&be[4] = *(const float4*)&beta[tid * 8 + 4];

    float r[8];
#pragma unroll
    for (int e = 0; e < 8; e++)
        r[e] = fmaf((v[e] - mu) * inv, g[e], be[e]);

    float* orow = &out[(size_t)row * D_DIM];
    *(float4*)&orow[tid * 8]     = make_float4(r[0], r[1], r[2], r[3]);
    *(float4*)&orow[tid * 8 + 4] = make_float4(r[4], r[5], r[6], r[7]);
}

// ---------------------------------------------------------------------------
extern "C" void kernel_launch(void* const* d_in, const int* in_sizes, int n_in,
                              void* d_out, int out_size)
{
    const float* x     = (const float*)d_in[0];
    const float* W_in  = (const float*)d_in[1];
    const float* W_fwd = (const float*)d_in[2];
    const float* W_bwd = (const float*)d_in[3];
    const float* W_out = (const float*)d_in[4];
    const float* gamma = (const float*)d_in[5];
    const float* beta  = (const float*)d_in[6];
    float* out = (float*)d_out;

    float *zab, *dgp, *op;
    uint8_t *xp, *zpk, *hp, *w1p, *w2p, *w3p;
    cudaGetSymbolAddress((void**)&zab, g_zab);
    cudaGetSymbolAddress((void**)&dgp, g_dg);
    cudaGetSymbolAddress((void**)&op,  g_out);
    cudaGetSymbolAddress((void**)&xp,  g_xp);
    cudaGetSymbolAddress((void**)&zpk, g_zp);
    cudaGetSymbolAddress((void**)&hp,  g_hp);
    cudaGetSymbolAddress((void**)&w1p, g_w1p);
    cudaGetSymbolAddress((void**)&w2p, g_w2p);
    cudaGetSymbolAddress((void**)&w3p, g_w3p);
    float* zp;
    cudaGetSymbolAddress((void**)&zp, g_z);

    cudaFuncSetAttribute((const void*)gemm_bf16x3<1>,
                         cudaFuncAttributeMaxDynamicSharedMemorySize, GSMEM);
    cudaFuncSetAttribute((const void*)gemm_bf16x3<2>,
                         cudaFuncAttributeMaxDynamicSharedMemorySize, GSMEM);
    cudaFuncSetAttribute((const void*)gemm_bf16x3<3>,
                         cudaFuncAttributeMaxDynamicSharedMemorySize, GSMEM);

    // operand preparation: pre-swizzled tile images
    prep_all<<<8416, 256>>>(x, W_in, W_fwd, W_bwd, W_out);

    // z partials: K-split GEMM1, grid (2 K-halves, 128 mtiles) = 256 CTAs
    gemm_bf16x3<1><<<dim3(2, M_TOTAL / 128), 256, GSMEM>>>(
        xp, w1p, zab, nullptr, nullptr, DI_DIM, D_DIM / 2);

    // z = za + zb (fp32) + packed zpk tiles
    z_combine<<<dim3(8, 128), 256>>>();

    // dg^T = act(z @ [W_fwd|W_bwd])^T
    gemm_bf16x3<2><<<dim3(4, M_TOTAL / 128), 256, GSMEM>>>(
        zpk, w2p, dgp, nullptr, zp, 1024, DI_DIM);

    // bidirectional gated scans -> h^T
    scan_kernel<<<dim3(DI_DIM, 4, 2), 256>>>();

    // h^T -> packed A-tiles
    h_pack<<<dim3(16, 128), 256>>>();

    // y = h @ W_out + x
    gemm_bf16x3<3><<<dim3(8, M_TOTAL / 128), 256, GSMEM>>>(
        hp, w3p, op, nullptr, x, D_DIM, 512);

    // LayerNorm
    ln_kernel<<<M_TOTAL, 256>>>(gamma, beta, out);
}